// round 1
// baseline (speedup 1.0000x reference)
#include <cuda_runtime.h>
#include <math.h>

#define NB  4
#define TW  1024
#define TE  128
#define TT  1152   // TW + TE
#define HD  1024
#define NHD 16
#define DHD 64

// ---------------- scratch (device globals; no allocation allowed) ----------------
__device__ float g_PE [NB*TE*HD];          // pos_ent
__device__ float g_Q  [NB*NHD*TT*DHD];     // also reused as word Y temp
__device__ float g_K  [NB*NHD*TT*DHD];     // also reused as ent  Y temp
__device__ float g_V  [NB*NHD*TT*DHD];
__device__ float g_CTX[NB*TT*HD];

// ---------------- pos_ent = (entity + query_pos) * 0.5 ----------------
__global__ void pe_kernel(const float* __restrict__ ent,
                          const float* __restrict__ qp,
                          float* __restrict__ pe) {
    int i = blockIdx.x * blockDim.x + threadIdx.x;
    float4 a = ((const float4*)ent)[i];
    float4 b = ((const float4*)qp)[i];
    float4 r;
    r.x = (a.x + b.x) * 0.5f;
    r.y = (a.y + b.y) * 0.5f;
    r.z = (a.z + b.z) * 0.5f;
    r.w = (a.w + b.w) * 0.5f;
    ((float4*)pe)[i] = r;
}

// ---------------- generic 128x128x8 SGEMM ----------------
// C[M,1024] = X[M,1024] @ W[1024,1024] (+ bias) (+ residual)
// Input rows are addressed through a (batch, token) decomposition so the same
// kernel reads both contiguous [B,Tseg,H] tensors and slices of CTX [B,TT,H].
// mode 0: scatter to head layout Q/K/V[((b*16+h)*TT + toffOut + t)*64 + d]
// mode 1: out[row*H+col] = acc + bias + residual[row*H+col]
__global__ __launch_bounds__(256) void gemm_kernel(
    const float* __restrict__ X, const float* __restrict__ W,
    const float* __restrict__ bias, const float* __restrict__ res,
    float* __restrict__ out,
    int TsegIn, int TfullIn, int toffIn, int mode, int toffOut)
{
    __shared__ float As[8][128];
    __shared__ float Bs[8][128];

    const int tid = threadIdx.x;
    const int bm = blockIdx.y * 128;
    const int bn = blockIdx.x * 128;
    const int tx = tid & 15;
    const int ty = tid >> 4;

    // X-tile loader indices: 2 threads per row, 4 cols each
    const int lr = tid >> 1;
    const int lh = tid & 1;
    {
        // precompute nothing heavy; do row mapping once
    }
    const int grow = bm + lr;
    const int bIn  = grow / TsegIn;
    const int tIn  = grow - bIn * TsegIn;
    const float* xrow = X + ((size_t)(bIn * TfullIn + toffIn + tIn)) * HD;

    // W-tile loader indices: 8 rows x 128 cols, float4
    const int wr = tid >> 5;
    const int wc = (tid & 31) * 4;

    float c[2][2][4][4];
    #pragma unroll
    for (int a = 0; a < 2; a++)
        #pragma unroll
        for (int b = 0; b < 2; b++)
            #pragma unroll
            for (int i = 0; i < 4; i++)
                #pragma unroll
                for (int j = 0; j < 4; j++) c[a][b][i][j] = 0.f;

    for (int kt = 0; kt < HD; kt += 8) {
        float4 xa = *(const float4*)(xrow + kt + lh * 4);
        float4 wb = *(const float4*)(W + (size_t)(kt + wr) * HD + bn + wc);
        __syncthreads();
        As[lh*4+0][lr] = xa.x;
        As[lh*4+1][lr] = xa.y;
        As[lh*4+2][lr] = xa.z;
        As[lh*4+3][lr] = xa.w;
        *(float4*)(&Bs[wr][wc]) = wb;
        __syncthreads();

        #pragma unroll
        for (int k = 0; k < 8; k++) {
            float4 a0 = *(const float4*)(&As[k][ty*4]);
            float4 a1 = *(const float4*)(&As[k][64 + ty*4]);
            float4 b0 = *(const float4*)(&Bs[k][tx*4]);
            float4 b1 = *(const float4*)(&Bs[k][64 + tx*4]);
            float av[2][4] = {{a0.x,a0.y,a0.z,a0.w},{a1.x,a1.y,a1.z,a1.w}};
            float bv[2][4] = {{b0.x,b0.y,b0.z,b0.w},{b1.x,b1.y,b1.z,b1.w}};
            #pragma unroll
            for (int ri = 0; ri < 2; ri++)
                #pragma unroll
                for (int i = 0; i < 4; i++)
                    #pragma unroll
                    for (int ci = 0; ci < 2; ci++)
                        #pragma unroll
                        for (int j = 0; j < 4; j++)
                            c[ri][ci][i][j] += av[ri][i] * bv[ci][j];
        }
    }

    // epilogue
    #pragma unroll
    for (int ri = 0; ri < 2; ri++) {
        #pragma unroll
        for (int i = 0; i < 4; i++) {
            int gr = bm + ri * 64 + ty * 4 + i;
            int b2 = gr / TsegIn;
            int t2 = gr - b2 * TsegIn;
            #pragma unroll
            for (int ci = 0; ci < 2; ci++) {
                #pragma unroll
                for (int j = 0; j < 4; j++) {
                    int gc = bn + ci * 64 + tx * 4 + j;
                    float v = c[ri][ci][i][j] + bias[gc];
                    if (mode == 0) {
                        int h = gc >> 6, d = gc & 63;
                        out[(((size_t)(b2 * NHD + h)) * TT + toffOut + t2) * DHD + d] = v;
                    } else {
                        size_t o = (size_t)gr * HD + gc;
                        out[o] = v + res[o];
                    }
                }
            }
        }
    }
}

// ---------------- flash attention ----------------
// Q,K,V: [B*NH, TT, 64]. One block: 128 query rows of one (b,h).
// 256 threads: 2 threads per row (each owns 32 output dims, 32 keys per tile).
__global__ __launch_bounds__(256) void attn_kernel(
    const float* __restrict__ Q, const float* __restrict__ K,
    const float* __restrict__ V, const float* __restrict__ mask,
    float* __restrict__ CTX)
{
    extern __shared__ float sm[];
    float* Qs = sm;                 // [128][68]
    float* Ks = sm + 128 * 68;      // [64][68]
    float* Vs = Ks + 64 * 68;       // [64][68]

    const int tid = threadIdx.x;
    const int bh = blockIdx.y;
    const int b  = bh >> 4, h = bh & 15;
    const int q0 = blockIdx.x * 128;

    const float* Qb = Q + ((size_t)bh * TT + q0) * DHD;
    const float* Kb = K + (size_t)bh * TT * DHD;
    const float* Vb = V + (size_t)bh * TT * DHD;
    const float* mb = mask + (size_t)b * TT;

    // load Q tile (128x64) into padded shared
    #pragma unroll
    for (int i = 0; i < 8; i++) {
        int idx = tid + i * 256;
        int r = idx >> 4, cc = (idx & 15) * 4;
        *(float4*)(Qs + r * 68 + cc) = *(const float4*)(Qb + r * DHD + cc);
    }
    __syncthreads();

    const int row  = tid >> 1;
    const int half = tid & 1;
    const float* qrow = Qs + row * 68;

    float O[32];
    #pragma unroll
    for (int i = 0; i < 32; i++) O[i] = 0.f;
    float m = -1e30f, l = 0.f;

    for (int kt = 0; kt < TT / 64; kt++) {
        __syncthreads();
        #pragma unroll
        for (int i = 0; i < 4; i++) {
            int idx = tid + i * 256;
            int r = idx >> 4, cc = (idx & 15) * 4;
            *(float4*)(Ks + r * 68 + cc) = *(const float4*)(Kb + (kt * 64 + r) * DHD + cc);
            *(float4*)(Vs + r * 68 + cc) = *(const float4*)(Vb + (kt * 64 + r) * DHD + cc);
        }
        __syncthreads();

        // scores: this thread's 32 keys are (2*kk + half)  -> conflict-free LDS
        float s[32];
        #pragma unroll
        for (int kk = 0; kk < 32; kk++) s[kk] = 0.f;
        #pragma unroll 1
        for (int d = 0; d < 64; d += 4) {
            float4 q4 = *(const float4*)(qrow + d);
            #pragma unroll
            for (int kk = 0; kk < 32; kk++) {
                float4 k4 = *(const float4*)(Ks + (2 * kk + half) * 68 + d);
                s[kk] += q4.x * k4.x + q4.y * k4.y + q4.z * k4.z + q4.w * k4.w;
            }
        }

        // scale + mask, online softmax
        float mt = -1e30f;
        #pragma unroll
        for (int kk = 0; kk < 32; kk++) {
            float sv = s[kk] * 0.125f + mb[kt * 64 + 2 * kk + half];
            s[kk] = sv;
            mt = fmaxf(mt, sv);
        }
        mt = fmaxf(mt, __shfl_xor_sync(0xffffffffu, mt, 1));
        float mnew  = fmaxf(m, mt);
        float alpha = __expf(m - mnew);
        float lloc = 0.f;
        #pragma unroll
        for (int kk = 0; kk < 32; kk++) {
            float p = __expf(s[kk] - mnew);
            s[kk] = p;
            lloc += p;
        }
        lloc += __shfl_xor_sync(0xffffffffu, lloc, 1);
        l = l * alpha + lloc;
        m = mnew;
        #pragma unroll
        for (int i = 0; i < 32; i++) O[i] *= alpha;

        // P @ V : exchange partner probabilities by pair-shuffle
        #pragma unroll
        for (int kk = 0; kk < 32; kk++) {
            float po = s[kk];
            float pp = __shfl_xor_sync(0xffffffffu, po, 1);
            float p0 = half ? pp : po;   // key 2*kk
            float p1 = half ? po : pp;   // key 2*kk+1
            const float* v0 = Vs + (2 * kk) * 68 + half * 32;
            const float* v1 = v0 + 68;
            #pragma unroll
            for (int dd = 0; dd < 32; dd += 4) {
                float4 a  = *(const float4*)(v0 + dd);
                float4 c4 = *(const float4*)(v1 + dd);
                O[dd+0] += p0 * a.x + p1 * c4.x;
                O[dd+1] += p0 * a.y + p1 * c4.y;
                O[dd+2] += p0 * a.z + p1 * c4.z;
                O[dd+3] += p0 * a.w + p1 * c4.w;
            }
        }
    }

    float inv = 1.f / l;
    float* dst = CTX + ((size_t)(b * TT + q0 + row)) * HD + h * DHD + half * 32;
    #pragma unroll
    for (int dd = 0; dd < 32; dd += 4) {
        float4 o4 = make_float4(O[dd] * inv, O[dd+1] * inv, O[dd+2] * inv, O[dd+3] * inv);
        *(float4*)(dst + dd) = o4;
    }
}

// ---------------- layernorm ----------------
__device__ __forceinline__ float block_sum(float v, float* sh) {
    #pragma unroll
    for (int o = 16; o; o >>= 1) v += __shfl_xor_sync(0xffffffffu, v, o);
    int tid = threadIdx.x;
    if ((tid & 31) == 0) sh[tid >> 5] = v;
    __syncthreads();
    if (tid < 32) {
        float t = (tid < 8) ? sh[tid] : 0.f;
        #pragma unroll
        for (int o = 4; o; o >>= 1) t += __shfl_xor_sync(0xffffffffu, t, o);
        if (tid == 0) sh[0] = t;
    }
    __syncthreads();
    float r = sh[0];
    __syncthreads();   // safe reuse of sh
    return r;
}

__global__ __launch_bounds__(256) void ln_kernel(
    const float* __restrict__ Y, const float* __restrict__ g,
    const float* __restrict__ bt, float* __restrict__ out)
{
    __shared__ float sh[8];
    int row = blockIdx.x, tid = threadIdx.x;
    float4 v = ((const float4*)(Y + (size_t)row * HD))[tid];
    float mu = block_sum(v.x + v.y + v.z + v.w, sh) * (1.f / HD);
    float4 d = make_float4(v.x - mu, v.y - mu, v.z - mu, v.w - mu);
    float var = block_sum(d.x*d.x + d.y*d.y + d.z*d.z + d.w*d.w, sh) * (1.f / HD);
    float rs = rsqrtf(var + 1e-12f);
    float4 gg = ((const float4*)g)[tid];
    float4 bb = ((const float4*)bt)[tid];
    float4 o = make_float4(d.x*rs*gg.x + bb.x, d.y*rs*gg.y + bb.y,
                           d.z*rs*gg.z + bb.z, d.w*rs*gg.w + bb.w);
    ((float4*)(out + (size_t)row * HD))[tid] = o;
}

// ---------------- launch ----------------
extern "C" void kernel_launch(void* const* d_in, const int* in_sizes, int n_in,
                              void* d_out, int out_size)
{
    (void)in_sizes; (void)n_in; (void)out_size;
    const float* word = (const float*)d_in[0];
    const float* ent  = (const float*)d_in[1];
    const float* mask = (const float*)d_in[2];
    const float* qpos = (const float*)d_in[3];
    const float* Wq  = (const float*)d_in[4];   const float* bq  = (const float*)d_in[5];
    const float* Wk  = (const float*)d_in[6];   const float* bk  = (const float*)d_in[7];
    const float* Wv  = (const float*)d_in[8];   const float* bv  = (const float*)d_in[9];
    const float* Weq = (const float*)d_in[10];  const float* beq = (const float*)d_in[11];
    const float* Wek = (const float*)d_in[12];  const float* bek = (const float*)d_in[13];
    const float* Wev = (const float*)d_in[14];  const float* bev = (const float*)d_in[15];
    const float* Wo  = (const float*)d_in[16];  const float* bo  = (const float*)d_in[17];
    const float* Weo = (const float*)d_in[18];  const float* beo = (const float*)d_in[19];
    const float* lng  = (const float*)d_in[20]; const float* lnb  = (const float*)d_in[21];
    const float* elng = (const float*)d_in[22]; const float* elnb = (const float*)d_in[23];
    float* out = (float*)d_out;

    float *PE, *Q, *K, *V, *CTX;
    cudaGetSymbolAddress((void**)&PE,  g_PE);
    cudaGetSymbolAddress((void**)&Q,   g_Q);
    cudaGetSymbolAddress((void**)&K,   g_K);
    cudaGetSymbolAddress((void**)&V,   g_V);
    cudaGetSymbolAddress((void**)&CTX, g_CTX);

    const int attn_smem = (128 * 68 + 2 * 64 * 68) * 4;   // 69632 B
    cudaFuncSetAttribute(attn_kernel, cudaFuncAttributeMaxDynamicSharedMemorySize, attn_smem);

    // 1. pos_ent
    pe_kernel<<<(NB * TE * HD / 4) / 256, 256>>>(ent, qpos, PE);

    // 2. projections into head layout
    dim3 gw(8, (NB * TW) / 128);   // (8, 32)
    dim3 ge(8, (NB * TE) / 128);   // (8, 4)
    gemm_kernel<<<gw, 256>>>(word, Wq,  bq,  nullptr, Q, TW, TW, 0, 0, 0);
    gemm_kernel<<<gw, 256>>>(word, Wk,  bk,  nullptr, K, TW, TW, 0, 0, 0);
    gemm_kernel<<<gw, 256>>>(word, Wv,  bv,  nullptr, V, TW, TW, 0, 0, 0);
    gemm_kernel<<<ge, 256>>>(PE,   Weq, beq, nullptr, Q, TE, TE, 0, 0, TW);
    gemm_kernel<<<ge, 256>>>(PE,   Wek, bek, nullptr, K, TE, TE, 0, 0, TW);
    gemm_kernel<<<ge, 256>>>(ent,  Wev, bev, nullptr, V, TE, TE, 0, 0, TW);

    // 3. attention -> CTX [B, TT, H]
    dim3 ga(TT / 128, NB * NHD);   // (9, 64)
    attn_kernel<<<ga, 256, attn_smem>>>(Q, K, V, mask, CTX);

    // 4. output projections + bias + residual (reuse Q/K scratch as Y temps)
    gemm_kernel<<<gw, 256>>>(CTX, Wo,  bo,  word, Q, TW, TT, 0,  1, 0);
    gemm_kernel<<<ge, 256>>>(CTX, Weo, beo, ent,  K, TE, TT, TW, 1, 0);

    // 5. layernorm -> d_out (word_out first, then ent_out)
    ln_kernel<<<NB * TW, 256>>>(Q, lng,  lnb,  out);
    ln_kernel<<<NB * TE, 256>>>(K, elng, elnb, out + (size_t)NB * TW * HD);
}

// round 3
// speedup vs baseline: 1.9863x; 1.9863x over previous
#include <cuda_runtime.h>
#include <cuda_bf16.h>
#include <stdint.h>
#include <math.h>

#define NB  4
#define TW  1024
#define TE  128
#define TT  1152
#define HD  1024
#define NHD 16
#define DHD 64

// ---------------- scratch ----------------
__device__ float g_Q  [NB*NHD*TT*DHD];     // fp32 q-proj; reused as word-Y temp
__device__ float g_K  [NB*NHD*TT*DHD];     // fp32 k-proj; reused as ent-Y temp
__device__ float g_V  [NB*NHD*TT*DHD];
__device__ float g_CTX[NB*TT*HD];
// prepped activations: rows 0..4095 word (or CTX rows 0..4607 later), 4096..4607 pos_ent, 4608..5119 ent
__device__ __nv_bfloat16 g_XHi[5120*1024];
__device__ __nv_bfloat16 g_XLo[5120*1024];
__device__ __nv_bfloat16 g_WtHi[8*1024*1024];
__device__ __nv_bfloat16 g_WtLo[8*1024*1024];

// ---------------- helpers ----------------
__device__ __forceinline__ uint32_t smem_u32(const void* p){
    uint32_t a;
    asm("{ .reg .u64 t; cvta.to.shared.u64 t, %1; cvt.u32.u64 %0, t; }" : "=r"(a) : "l"(p));
    return a;
}
__device__ __forceinline__ uint32_t pkb(__nv_bfloat16 a, __nv_bfloat16 b){
    uint16_t ua = *reinterpret_cast<uint16_t*>(&a);
    uint16_t ub = *reinterpret_cast<uint16_t*>(&b);
    return (uint32_t)ua | ((uint32_t)ub << 16);
}
__device__ __forceinline__ void splitf(float f, __nv_bfloat16& h, __nv_bfloat16& l){
    h = __float2bfloat16_rn(f);
    l = __float2bfloat16_rn(f - __bfloat162float(h));
}

#define CPA16(dst, src) asm volatile("cp.async.cg.shared.global [%0], [%1], 16;" :: "r"(dst), "l"(src))
#define CPA_COMMIT()    asm volatile("cp.async.commit_group;" ::: "memory")
template<int N> __device__ __forceinline__ void cpa_wait(){
    asm volatile("cp.async.wait_group %0;" :: "n"(N) : "memory");
}

__device__ __forceinline__ void ldsm4(uint32_t* r, uint32_t addr){
    asm volatile("ldmatrix.sync.aligned.m8n8.x4.shared.b16 {%0,%1,%2,%3}, [%4];"
        : "=r"(r[0]), "=r"(r[1]), "=r"(r[2]), "=r"(r[3]) : "r"(addr));
}
__device__ __forceinline__ void mma16816(float* d, const uint32_t* a, const uint32_t* b){
    asm volatile("mma.sync.aligned.m16n8k16.row.col.f32.bf16.bf16.f32 "
        "{%0,%1,%2,%3}, {%4,%5,%6,%7}, {%8,%9}, {%0,%1,%2,%3};"
        : "+f"(d[0]), "+f"(d[1]), "+f"(d[2]), "+f"(d[3])
        : "r"(a[0]), "r"(a[1]), "r"(a[2]), "r"(a[3]), "r"(b[0]), "r"(b[1]));
}

// ---------------- weight prep: transpose + bf16 hi/lo split ----------------
struct W8 { const float* p[8]; };

__global__ __launch_bounds__(256) void wprep_kernel(W8 ws, __nv_bfloat16* hiB, __nv_bfloat16* loB){
    __shared__ float tile[32][33];
    const float* W = ws.p[blockIdx.z];
    int n0 = blockIdx.x * 32, k0 = blockIdx.y * 32;
    int tx = threadIdx.x & 31, ty = threadIdx.x >> 5;
    #pragma unroll
    for (int i = 0; i < 32; i += 8)
        tile[ty + i][tx] = W[(size_t)(k0 + ty + i) * 1024 + n0 + tx];
    __syncthreads();
    #pragma unroll
    for (int i = 0; i < 32; i += 8) {
        float f = tile[tx][ty + i];
        __nv_bfloat16 h, l; splitf(f, h, l);
        size_t o = ((size_t)blockIdx.z << 20) + ((size_t)(n0 + ty + i) << 10) + k0 + tx;
        hiB[o] = h;
        loB[o] = l;
    }
}

// ---------------- activation prep (fp32 -> bf16 hi/lo) ----------------
__global__ void xprep_kernel(const float* __restrict__ X,
                             __nv_bfloat16* __restrict__ hi, __nv_bfloat16* __restrict__ lo){
    size_t i = (size_t)blockIdx.x * blockDim.x + threadIdx.x;
    float4 v = ((const float4*)X)[i];
    __nv_bfloat16 h0,h1,h2,h3,l0,l1,l2,l3;
    splitf(v.x,h0,l0); splitf(v.y,h1,l1); splitf(v.z,h2,l2); splitf(v.w,h3,l3);
    ((uint2*)hi)[i] = make_uint2(pkb(h0,h1), pkb(h2,h3));
    ((uint2*)lo)[i] = make_uint2(pkb(l0,l1), pkb(l2,l3));
}

// pos_ent = (ent + qp) * 0.5, directly split
__global__ void pexprep_kernel(const float* __restrict__ ent, const float* __restrict__ qp,
                               __nv_bfloat16* __restrict__ hi, __nv_bfloat16* __restrict__ lo){
    size_t i = (size_t)blockIdx.x * blockDim.x + threadIdx.x;
    float4 a = ((const float4*)ent)[i];
    float4 b = ((const float4*)qp)[i];
    float4 v = make_float4((a.x+b.x)*0.5f,(a.y+b.y)*0.5f,(a.z+b.z)*0.5f,(a.w+b.w)*0.5f);
    __nv_bfloat16 h0,h1,h2,h3,l0,l1,l2,l3;
    splitf(v.x,h0,l0); splitf(v.y,h1,l1); splitf(v.z,h2,l2); splitf(v.w,h3,l3);
    ((uint2*)hi)[i] = make_uint2(pkb(h0,h1), pkb(h2,h3));
    ((uint2*)lo)[i] = make_uint2(pkb(l0,l1), pkb(l2,l3));
}

// ---------------- split-bf16 HMMA GEMM ----------------
// C[M,1024] = X[M,1024] @ W[1024,1024]; D = Ahi*Bhi + Ahi*Blo + Alo*Bhi (fp32 acc)
// CTA: 128(M) x 128(N); K chunks of 64, cp.async double buffered.
// SMEM buffer layout (per buf, 73728 B): AHi[128x72], ALo, BHi[128x72], BLo (bf16, stride 72)
#define STRB  144            // 72 bf16 * 2B
#define OFF_ALO 18432
#define OFF_BHI 36864
#define BUFSZ  73728
#define SMEM_GEMM (2*BUFSZ)  // 147456

struct GemmCfg {
    const float* b0; const float* b1; const float* b2;
    float* o0; float* o1; float* o2;
    const float* res;
    int widx0, Tseg, Tfull, toff, mode, toffOut;
    int xbase01, xbase2;
};

__global__ __launch_bounds__(256) void gemm_mma(
    const __nv_bfloat16* __restrict__ XHi, const __nv_bfloat16* __restrict__ XLo,
    const __nv_bfloat16* __restrict__ WHiAll, const __nv_bfloat16* __restrict__ WLoAll,
    GemmCfg cfg)
{
    extern __shared__ char smc[];
    const uint32_t sb = smem_u32(smc);
    const int tid = threadIdx.x;
    const int wid = tid >> 5, lane = tid & 31;
    const int wm = wid >> 1, wn = wid & 1;
    const int z = blockIdx.z;

    const float* bias = (z == 0) ? cfg.b0 : (z == 1) ? cfg.b1 : cfg.b2;
    float* out        = (z == 0) ? cfg.o0 : (z == 1) ? cfg.o1 : cfg.o2;
    const __nv_bfloat16* WHi = WHiAll + ((size_t)(cfg.widx0 + z) << 20);
    const __nv_bfloat16* WLo = WLoAll + ((size_t)(cfg.widx0 + z) << 20);

    const int m0 = blockIdx.y * 128;
    const int n0 = blockIdx.x * 128;
    const int b2 = m0 / cfg.Tseg;
    const int t0 = m0 - b2 * cfg.Tseg;
    const int xbase = (z == 2) ? cfg.xbase2 : cfg.xbase01;
    const size_t xrow0 = (size_t)xbase + (size_t)b2 * cfg.Tfull + cfg.toff + t0;
    const __nv_bfloat16* Ah = XHi + xrow0 * HD;
    const __nv_bfloat16* Al = XLo + xrow0 * HD;

    // per-thread load mapping: 4 iters, each covers (row = q>>3, 16B seg = q&7)
    const int lrow = tid >> 1;            // unused alt mapping
    (void)lrow;

    float acc[2][8][4];
    #pragma unroll
    for (int mt = 0; mt < 2; mt++)
        #pragma unroll
        for (int nt = 0; nt < 8; nt++)
            #pragma unroll
            for (int j = 0; j < 4; j++) acc[mt][nt][j] = 0.f;

    // issue loads for chunk ch into buffer buf
    auto issue_chunk = [&](int ch, int buf){
        const int k0 = ch * 64;
        const uint32_t base = sb + buf * BUFSZ;
        #pragma unroll
        for (int i = 0; i < 4; i++) {
            int q = tid + i * 256;          // 0..1023
            int r = q >> 3, s8 = q & 7;
            uint32_t da = base + r * STRB + s8 * 16;
            const __nv_bfloat16* sa = Ah + (size_t)r * HD + k0 + s8 * 8;
            const __nv_bfloat16* sal = Al + (size_t)r * HD + k0 + s8 * 8;
            CPA16(da, sa);
            CPA16(da + OFF_ALO, sal);
            uint32_t db = base + OFF_BHI + r * STRB + s8 * 16;
            const __nv_bfloat16* sbh = WHi + (size_t)(n0 + r) * HD + k0 + s8 * 8;
            const __nv_bfloat16* sbl = WLo + (size_t)(n0 + r) * HD + k0 + s8 * 8;
            CPA16(db, sbh);
            CPA16(db + OFF_ALO, sbl);
        }
    };

    issue_chunk(0, 0);
    CPA_COMMIT();

    const int arow = (lane & 7) + ((lane >> 3) & 1) * 8;
    const int acol8 = (lane >> 4) * 8;
    const int bnof = (lane & 7) + ((lane >> 4) << 3);
    const int bk8  = ((lane >> 3) & 1) * 8;

    int buf = 0;
    for (int ch = 0; ch < 16; ch++) {
        if (ch < 15) { issue_chunk(ch + 1, buf ^ 1); CPA_COMMIT(); cpa_wait<1>(); }
        else         { cpa_wait<0>(); }
        __syncthreads();

        const uint32_t base = sb + buf * BUFSZ;
        #pragma unroll
        for (int ks = 0; ks < 4; ks++) {
            uint32_t aF[2][2][4];
            #pragma unroll
            for (int mt = 0; mt < 2; mt++) {
                uint32_t ad = base + (wm*32 + mt*16 + arow) * STRB + (ks*16 + acol8) * 2;
                ldsm4(aF[0][mt], ad);
                ldsm4(aF[1][mt], ad + OFF_ALO);
            }
            uint32_t bF[2][4][4];
            #pragma unroll
            for (int np = 0; np < 4; np++) {
                uint32_t bd = base + OFF_BHI + (wn*64 + np*16 + bnof) * STRB + (ks*16 + bk8) * 2;
                ldsm4(bF[0][np], bd);
                ldsm4(bF[1][np], bd + OFF_ALO);
            }
            #pragma unroll
            for (int mt = 0; mt < 2; mt++) {
                #pragma unroll
                for (int nt = 0; nt < 8; nt++) {
                    const uint32_t* bh = &bF[0][nt >> 1][(nt & 1) * 2];
                    const uint32_t* bl = &bF[1][nt >> 1][(nt & 1) * 2];
                    mma16816(acc[mt][nt], aF[0][mt], bh);
                    mma16816(acc[mt][nt], aF[0][mt], bl);
                    mma16816(acc[mt][nt], aF[1][mt], bh);
                }
            }
        }
        __syncthreads();
        buf ^= 1;
    }

    // ---- epilogue: direct stores from accumulators ----
    #pragma unroll
    for (int mt = 0; mt < 2; mt++) {
        #pragma unroll
        for (int hf = 0; hf < 2; hf++) {
            int lr = wm*32 + mt*16 + (lane >> 2) + hf*8;
            int t2 = t0 + lr;
            #pragma unroll
            for (int nt = 0; nt < 8; nt++) {
                int c = n0 + wn*64 + nt*8 + (lane & 3)*2;
                float v0 = acc[mt][nt][hf*2+0] + __ldg(bias + c);
                float v1 = acc[mt][nt][hf*2+1] + __ldg(bias + c + 1);
                if (cfg.mode == 0) {
                    int h = c >> 6, d = c & 63;
                    size_t o = (((size_t)(b2*NHD + h) * TT + cfg.toffOut + t2) << 6) + d;
                    *(float2*)(out + o) = make_float2(v0, v1);
                } else {
                    size_t o = (size_t)(m0 + lr) * HD + c;
                    float2 rr = *(const float2*)(cfg.res + o);
                    *(float2*)(out + o) = make_float2(v0 + rr.x, v1 + rr.y);
                }
            }
        }
    }
}

// ---------------- flash attention (fp32) ----------------
__global__ __launch_bounds__(256) void attn_kernel(
    const float* __restrict__ Q, const float* __restrict__ K,
    const float* __restrict__ V, const float* __restrict__ mask,
    float* __restrict__ CTX)
{
    extern __shared__ float sm[];
    float* Qs = sm;
    float* Ks = sm + 128 * 68;
    float* Vs = Ks + 64 * 68;

    const int tid = threadIdx.x;
    const int bh = blockIdx.y;
    const int b = bh >> 4, h = bh & 15;
    const int q0 = blockIdx.x * 128;

    const float* Qb = Q + ((size_t)bh * TT + q0) * DHD;
    const float* Kb = K + (size_t)bh * TT * DHD;
    const float* Vb = V + (size_t)bh * TT * DHD;
    const float* mb = mask + (size_t)b * TT;

    #pragma unroll
    for (int i = 0; i < 8; i++) {
        int idx = tid + i * 256;
        int r = idx >> 4, cc = (idx & 15) * 4;
        *(float4*)(Qs + r * 68 + cc) = *(const float4*)(Qb + r * DHD + cc);
    }
    __syncthreads();

    const int row = tid >> 1;
    const int half = tid & 1;
    const float* qrow = Qs + row * 68;

    float O[32];
    #pragma unroll
    for (int i = 0; i < 32; i++) O[i] = 0.f;
    float m = -1e30f, l = 0.f;

    for (int kt = 0; kt < TT / 64; kt++) {
        __syncthreads();
        #pragma unroll
        for (int i = 0; i < 4; i++) {
            int idx = tid + i * 256;
            int r = idx >> 4, cc = (idx & 15) * 4;
            *(float4*)(Ks + r * 68 + cc) = *(const float4*)(Kb + (kt * 64 + r) * DHD + cc);
            *(float4*)(Vs + r * 68 + cc) = *(const float4*)(Vb + (kt * 64 + r) * DHD + cc);
        }
        __syncthreads();

        float s[32];
        #pragma unroll
        for (int kk = 0; kk < 32; kk++) s[kk] = 0.f;
        #pragma unroll 1
        for (int d = 0; d < 64; d += 4) {
            float4 q4 = *(const float4*)(qrow + d);
            #pragma unroll
            for (int kk = 0; kk < 32; kk++) {
                float4 k4 = *(const float4*)(Ks + (2 * kk + half) * 68 + d);
                s[kk] += q4.x * k4.x + q4.y * k4.y + q4.z * k4.z + q4.w * k4.w;
            }
        }

        float mt = -1e30f;
        #pragma unroll
        for (int kk = 0; kk < 32; kk++) {
            float sv = s[kk] * 0.125f + mb[kt * 64 + 2 * kk + half];
            s[kk] = sv;
            mt = fmaxf(mt, sv);
        }
        mt = fmaxf(mt, __shfl_xor_sync(0xffffffffu, mt, 1));
        float mnew = fmaxf(m, mt);
        float alpha = __expf(m - mnew);
        float lloc = 0.f;
        #pragma unroll
        for (int kk = 0; kk < 32; kk++) {
            float p = __expf(s[kk] - mnew);
            s[kk] = p;
            lloc += p;
        }
        lloc += __shfl_xor_sync(0xffffffffu, lloc, 1);
        l = l * alpha + lloc;
        m = mnew;
        #pragma unroll
        for (int i = 0; i < 32; i++) O[i] *= alpha;

        #pragma unroll
        for (int kk = 0; kk < 32; kk++) {
            float po = s[kk];
            float pp = __shfl_xor_sync(0xffffffffu, po, 1);
            float p0 = half ? pp : po;
            float p1 = half ? po : pp;
            const float* v0 = Vs + (2 * kk) * 68 + half * 32;
            const float* v1 = v0 + 68;
            #pragma unroll
            for (int dd = 0; dd < 32; dd += 4) {
                float4 a = *(const float4*)(v0 + dd);
                float4 c4 = *(const float4*)(v1 + dd);
                O[dd+0] += p0 * a.x + p1 * c4.x;
                O[dd+1] += p0 * a.y + p1 * c4.y;
                O[dd+2] += p0 * a.z + p1 * c4.z;
                O[dd+3] += p0 * a.w + p1 * c4.w;
            }
        }
    }

    float inv = 1.f / l;
    float* dst = CTX + ((size_t)(b * TT + q0 + row)) * HD + h * DHD + half * 32;
    #pragma unroll
    for (int dd = 0; dd < 32; dd += 4) {
        *(float4*)(dst + dd) = make_float4(O[dd]*inv, O[dd+1]*inv, O[dd+2]*inv, O[dd+3]*inv);
    }
}

// ---------------- layernorm ----------------
__device__ __forceinline__ float block_sum(float v, float* sh) {
    #pragma unroll
    for (int o = 16; o; o >>= 1) v += __shfl_xor_sync(0xffffffffu, v, o);
    int tid = threadIdx.x;
    if ((tid & 31) == 0) sh[tid >> 5] = v;
    __syncthreads();
    if (tid < 32) {
        float t = (tid < 8) ? sh[tid] : 0.f;
        #pragma unroll
        for (int o = 4; o; o >>= 1) t += __shfl_xor_sync(0xffffffffu, t, o);
        if (tid == 0) sh[0] = t;
    }
    __syncthreads();
    float r = sh[0];
    __syncthreads();
    return r;
}

__global__ __launch_bounds__(256) void ln_kernel(
    const float* __restrict__ Y, const float* __restrict__ g,
    const float* __restrict__ bt, float* __restrict__ out)
{
    __shared__ float sh[8];
    int row = blockIdx.x, tid = threadIdx.x;
    float4 v = ((const float4*)(Y + (size_t)row * HD))[tid];
    float mu = block_sum(v.x + v.y + v.z + v.w, sh) * (1.f / HD);
    float4 d = make_float4(v.x - mu, v.y - mu, v.z - mu, v.w - mu);
    float var = block_sum(d.x*d.x + d.y*d.y + d.z*d.z + d.w*d.w, sh) * (1.f / HD);
    float rs = rsqrtf(var + 1e-12f);
    float4 gg = ((const float4*)g)[tid];
    float4 bb = ((const float4*)bt)[tid];
    ((float4*)(out + (size_t)row * HD))[tid] =
        make_float4(d.x*rs*gg.x + bb.x, d.y*rs*gg.y + bb.y, d.z*rs*gg.z + bb.z, d.w*rs*gg.w + bb.w);
}

// ---------------- launch ----------------
extern "C" void kernel_launch(void* const* d_in, const int* in_sizes, int n_in,
                              void* d_out, int out_size)
{
    (void)in_sizes; (void)n_in; (void)out_size;
    const float* word = (const float*)d_in[0];
    const float* ent  = (const float*)d_in[1];
    const float* mask = (const float*)d_in[2];
    const float* qpos = (const float*)d_in[3];
    const float* Wq  = (const float*)d_in[4];   const float* bq  = (const float*)d_in[5];
    const float* Wk  = (const float*)d_in[6];   const float* bk  = (const float*)d_in[7];
    const float* Wv  = (const float*)d_in[8];   const float* bv  = (const float*)d_in[9];
    const float* Weq = (const float*)d_in[10];  const float* beq = (const float*)d_in[11];
    const float* Wek = (const float*)d_in[12];  const float* bek = (const float*)d_in[13];
    const float* Wev = (const float*)d_in[14];  const float* bev = (const float*)d_in[15];
    const float* Wo  = (const float*)d_in[16];  const float* bo  = (const float*)d_in[17];
    const float* Weo = (const float*)d_in[18];  const float* beo = (const float*)d_in[19];
    const float* lng  = (const float*)d_in[20]; const float* lnb  = (const float*)d_in[21];
    const float* elng = (const float*)d_in[22]; const float* elnb = (const float*)d_in[23];
    float* out = (float*)d_out;

    float *Q, *K, *V, *CTX;
    __nv_bfloat16 *XHi, *XLo, *WtHi, *WtLo;
    cudaGetSymbolAddress((void**)&Q,    g_Q);
    cudaGetSymbolAddress((void**)&K,    g_K);
    cudaGetSymbolAddress((void**)&V,    g_V);
    cudaGetSymbolAddress((void**)&CTX,  g_CTX);
    cudaGetSymbolAddress((void**)&XHi,  g_XHi);
    cudaGetSymbolAddress((void**)&XLo,  g_XLo);
    cudaGetSymbolAddress((void**)&WtHi, g_WtHi);
    cudaGetSymbolAddress((void**)&WtLo, g_WtLo);

    cudaFuncSetAttribute(gemm_mma, cudaFuncAttributeMaxDynamicSharedMemorySize, SMEM_GEMM);
    const int attn_smem = (128 * 68 + 2 * 64 * 68) * 4;
    cudaFuncSetAttribute(attn_kernel, cudaFuncAttributeMaxDynamicSharedMemorySize, attn_smem);

    // 0. weight prep (transpose + split)
    W8 w8; w8.p[0]=Wq; w8.p[1]=Wk; w8.p[2]=Wv; w8.p[3]=Weq; w8.p[4]=Wek; w8.p[5]=Wev; w8.p[6]=Wo; w8.p[7]=Weo;
    wprep_kernel<<<dim3(32, 32, 8), 256>>>(w8, WtHi, WtLo);

    // 1. activation prep: word rows [0,4096), pos_ent rows [4096,4608), ent rows [4608,5120)
    xprep_kernel <<<(NB*TW*HD/4)/256, 256>>>(word, XHi, XLo);
    pexprep_kernel<<<(NB*TE*HD/4)/256, 256>>>(ent, qpos, XHi + (size_t)4096*HD, XLo + (size_t)4096*HD);
    xprep_kernel <<<(NB*TE*HD/4)/256, 256>>>(ent, XHi + (size_t)4608*HD, XLo + (size_t)4608*HD);

    // 2. projections (HMMA)
    GemmCfg c1 = {};
    c1.b0 = bq; c1.b1 = bk; c1.b2 = bv;
    c1.o0 = Q; c1.o1 = K; c1.o2 = V;
    c1.widx0 = 0; c1.Tseg = TW; c1.Tfull = TW; c1.toff = 0; c1.mode = 0; c1.toffOut = 0;
    c1.xbase01 = 0; c1.xbase2 = 0;
    gemm_mma<<<dim3(8, (NB*TW)/128, 3), 256, SMEM_GEMM>>>(XHi, XLo, WtHi, WtLo, c1);

    GemmCfg c2 = {};
    c2.b0 = beq; c2.b1 = bek; c2.b2 = bev;
    c2.o0 = Q; c2.o1 = K; c2.o2 = V;
    c2.widx0 = 3; c2.Tseg = TE; c2.Tfull = TE; c2.toff = 0; c2.mode = 0; c2.toffOut = TW;
    c2.xbase01 = 4096; c2.xbase2 = 4608;
    gemm_mma<<<dim3(8, (NB*TE)/128, 3), 256, SMEM_GEMM>>>(XHi, XLo, WtHi, WtLo, c2);

    // 3. attention -> CTX
    dim3 ga(TT / 128, NB * NHD);
    attn_kernel<<<ga, 256, attn_smem>>>(Q, K, V, mask, CTX);

    // 4. CTX prep (rows [0,4608)) + output projections + residual
    xprep_kernel<<<(NB*TT*HD/4)/256, 256>>>(CTX, XHi, XLo);

    GemmCfg c3 = {};
    c3.b0 = bo; c3.o0 = Q; c3.res = word;
    c3.widx0 = 6; c3.Tseg = TW; c3.Tfull = TT; c3.toff = 0; c3.mode = 1;
    c3.xbase01 = 0; c3.xbase2 = 0;
    gemm_mma<<<dim3(8, (NB*TW)/128, 1), 256, SMEM_GEMM>>>(XHi, XLo, WtHi, WtLo, c3);

    GemmCfg c4 = {};
    c4.b0 = beo; c4.o0 = K; c4.res = ent;
    c4.widx0 = 7; c4.Tseg = TE; c4.Tfull = TT; c4.toff = TW; c4.mode = 1;
    c4.xbase01 = 0; c4.xbase2 = 0;
    gemm_mma<<<dim3(8, (NB*TE)/128, 1), 256, SMEM_GEMM>>>(XHi, XLo, WtHi, WtLo, c4);

    // 5. layernorm
    ln_kernel<<<NB * TW, 256>>>(Q, lng, lnb, out);
    ln_kernel<<<NB * TE, 256>>>(K, elng, elnb, out + (size_t)NB * TW * HD);
}

// round 4
// speedup vs baseline: 4.1059x; 2.0671x over previous
#include <cuda_runtime.h>
#include <cuda_bf16.h>
#include <stdint.h>
#include <math.h>

#define NB  4
#define TW  1024
#define TE  128
#define TT  1152
#define HD  1024
#define NHD 16
#define DHD 64

// ---------------- scratch ----------------
__device__ float g_Q  [NB*NHD*TT*DHD];     // fp32 q-proj; reused as word-Y temp
__device__ float g_K  [NB*NHD*TT*DHD];     // fp32 k-proj; reused as ent-Y temp
__device__ float g_V  [NB*NHD*TT*DHD];
__device__ float g_CTX[NB*TT*HD];
__device__ __nv_bfloat16 g_XHi[5120*1024];
__device__ __nv_bfloat16 g_XLo[5120*1024];
__device__ __nv_bfloat16 g_WtHi[8*1024*1024];
__device__ __nv_bfloat16 g_WtLo[8*1024*1024];

// ---------------- helpers ----------------
__device__ __forceinline__ uint32_t smem_u32(const void* p){
    uint32_t a;
    asm("{ .reg .u64 t; cvta.to.shared.u64 t, %1; cvt.u32.u64 %0, t; }" : "=r"(a) : "l"(p));
    return a;
}
__device__ __forceinline__ uint32_t pkb(__nv_bfloat16 a, __nv_bfloat16 b){
    uint16_t ua = *reinterpret_cast<uint16_t*>(&a);
    uint16_t ub = *reinterpret_cast<uint16_t*>(&b);
    return (uint32_t)ua | ((uint32_t)ub << 16);
}
__device__ __forceinline__ void splitf(float f, __nv_bfloat16& h, __nv_bfloat16& l){
    h = __float2bfloat16_rn(f);
    l = __float2bfloat16_rn(f - __bfloat162float(h));
}
__device__ __forceinline__ uint32_t f2tf32(float f){
    uint32_t u; asm("cvt.rna.tf32.f32 %0, %1;" : "=r"(u) : "f"(f)); return u;
}

#define CPA16(dst, src) asm volatile("cp.async.cg.shared.global [%0], [%1], 16;" :: "r"(dst), "l"(src))
#define CPA_COMMIT()    asm volatile("cp.async.commit_group;" ::: "memory")
template<int N> __device__ __forceinline__ void cpa_wait(){
    asm volatile("cp.async.wait_group %0;" :: "n"(N) : "memory");
}

__device__ __forceinline__ void ldsm4(uint32_t* r, uint32_t addr){
    asm volatile("ldmatrix.sync.aligned.m8n8.x4.shared.b16 {%0,%1,%2,%3}, [%4];"
        : "=r"(r[0]), "=r"(r[1]), "=r"(r[2]), "=r"(r[3]) : "r"(addr));
}
__device__ __forceinline__ void mma16816(float* d, const uint32_t* a, const uint32_t* b){
    asm volatile("mma.sync.aligned.m16n8k16.row.col.f32.bf16.bf16.f32 "
        "{%0,%1,%2,%3}, {%4,%5,%6,%7}, {%8,%9}, {%0,%1,%2,%3};"
        : "+f"(d[0]), "+f"(d[1]), "+f"(d[2]), "+f"(d[3])
        : "r"(a[0]), "r"(a[1]), "r"(a[2]), "r"(a[3]), "r"(b[0]), "r"(b[1]));
}
__device__ __forceinline__ void mma_tf32(float* d, const uint32_t* a, const uint32_t* b){
    asm volatile("mma.sync.aligned.m16n8k8.row.col.f32.tf32.tf32.f32 "
        "{%0,%1,%2,%3}, {%4,%5,%6,%7}, {%8,%9}, {%0,%1,%2,%3};"
        : "+f"(d[0]), "+f"(d[1]), "+f"(d[2]), "+f"(d[3])
        : "r"(a[0]), "r"(a[1]), "r"(a[2]), "r"(a[3]), "r"(b[0]), "r"(b[1]));
}

// ---------------- weight prep: transpose + bf16 hi/lo split ----------------
struct W8 { const float* p[8]; };

__global__ __launch_bounds__(256) void wprep_kernel(W8 ws, __nv_bfloat16* hiB, __nv_bfloat16* loB){
    __shared__ float tile[32][33];
    const float* W = ws.p[blockIdx.z];
    int n0 = blockIdx.x * 32, k0 = blockIdx.y * 32;
    int tx = threadIdx.x & 31, ty = threadIdx.x >> 5;
    #pragma unroll
    for (int i = 0; i < 32; i += 8)
        tile[ty + i][tx] = W[(size_t)(k0 + ty + i) * 1024 + n0 + tx];
    __syncthreads();
    #pragma unroll
    for (int i = 0; i < 32; i += 8) {
        float f = tile[tx][ty + i];
        __nv_bfloat16 h, l; splitf(f, h, l);
        size_t o = ((size_t)blockIdx.z << 20) + ((size_t)(n0 + ty + i) << 10) + k0 + tx;
        hiB[o] = h;
        loB[o] = l;
    }
}

// ---------------- activation prep (fp32 -> bf16 hi/lo) ----------------
__global__ void xprep_kernel(const float* __restrict__ X,
                             __nv_bfloat16* __restrict__ hi, __nv_bfloat16* __restrict__ lo){
    size_t i = (size_t)blockIdx.x * blockDim.x + threadIdx.x;
    float4 v = ((const float4*)X)[i];
    __nv_bfloat16 h0,h1,h2,h3,l0,l1,l2,l3;
    splitf(v.x,h0,l0); splitf(v.y,h1,l1); splitf(v.z,h2,l2); splitf(v.w,h3,l3);
    ((uint2*)hi)[i] = make_uint2(pkb(h0,h1), pkb(h2,h3));
    ((uint2*)lo)[i] = make_uint2(pkb(l0,l1), pkb(l2,l3));
}

__global__ void pexprep_kernel(const float* __restrict__ ent, const float* __restrict__ qp,
                               __nv_bfloat16* __restrict__ hi, __nv_bfloat16* __restrict__ lo){
    size_t i = (size_t)blockIdx.x * blockDim.x + threadIdx.x;
    float4 a = ((const float4*)ent)[i];
    float4 b = ((const float4*)qp)[i];
    float4 v = make_float4((a.x+b.x)*0.5f,(a.y+b.y)*0.5f,(a.z+b.z)*0.5f,(a.w+b.w)*0.5f);
    __nv_bfloat16 h0,h1,h2,h3,l0,l1,l2,l3;
    splitf(v.x,h0,l0); splitf(v.y,h1,l1); splitf(v.z,h2,l2); splitf(v.w,h3,l3);
    ((uint2*)hi)[i] = make_uint2(pkb(h0,h1), pkb(h2,h3));
    ((uint2*)lo)[i] = make_uint2(pkb(l0,l1), pkb(l2,l3));
}

// ---------------- split-bf16 HMMA GEMM ----------------
#define STRB  144
#define OFF_ALO 18432
#define OFF_BHI 36864
#define BUFSZ  73728
#define SMEM_GEMM (2*BUFSZ)

struct GemmCfg {
    const float* b0; const float* b1; const float* b2;
    float* o0; float* o1; float* o2;
    const float* res;
    int widx0, Tseg, Tfull, toff, mode, toffOut;
    int xbase01, xbase2;
};

__global__ __launch_bounds__(256) void gemm_mma(
    const __nv_bfloat16* __restrict__ XHi, const __nv_bfloat16* __restrict__ XLo,
    const __nv_bfloat16* __restrict__ WHiAll, const __nv_bfloat16* __restrict__ WLoAll,
    GemmCfg cfg)
{
    extern __shared__ char smc[];
    const uint32_t sb = smem_u32(smc);
    const int tid = threadIdx.x;
    const int wid = tid >> 5, lane = tid & 31;
    const int wm = wid >> 1, wn = wid & 1;
    const int z = blockIdx.z;

    const float* bias = (z == 0) ? cfg.b0 : (z == 1) ? cfg.b1 : cfg.b2;
    float* out        = (z == 0) ? cfg.o0 : (z == 1) ? cfg.o1 : cfg.o2;
    const __nv_bfloat16* WHi = WHiAll + ((size_t)(cfg.widx0 + z) << 20);
    const __nv_bfloat16* WLo = WLoAll + ((size_t)(cfg.widx0 + z) << 20);

    const int m0 = blockIdx.y * 128;
    const int n0 = blockIdx.x * 128;
    const int b2 = m0 / cfg.Tseg;
    const int t0 = m0 - b2 * cfg.Tseg;
    const int xbase = (z == 2) ? cfg.xbase2 : cfg.xbase01;
    const size_t xrow0 = (size_t)xbase + (size_t)b2 * cfg.Tfull + cfg.toff + t0;
    const __nv_bfloat16* Ah = XHi + xrow0 * HD;
    const __nv_bfloat16* Al = XLo + xrow0 * HD;

    float acc[2][8][4];
    #pragma unroll
    for (int mt = 0; mt < 2; mt++)
        #pragma unroll
        for (int nt = 0; nt < 8; nt++)
            #pragma unroll
            for (int j = 0; j < 4; j++) acc[mt][nt][j] = 0.f;

    auto issue_chunk = [&](int ch, int buf){
        const int k0 = ch * 64;
        const uint32_t base = sb + buf * BUFSZ;
        #pragma unroll
        for (int i = 0; i < 4; i++) {
            int q = tid + i * 256;
            int r = q >> 3, s8 = q & 7;
            uint32_t da = base + r * STRB + s8 * 16;
            CPA16(da, Ah + (size_t)r * HD + k0 + s8 * 8);
            CPA16(da + OFF_ALO, Al + (size_t)r * HD + k0 + s8 * 8);
            uint32_t db = base + OFF_BHI + r * STRB + s8 * 16;
            CPA16(db, WHi + (size_t)(n0 + r) * HD + k0 + s8 * 8);
            CPA16(db + OFF_ALO, WLo + (size_t)(n0 + r) * HD + k0 + s8 * 8);
        }
    };

    issue_chunk(0, 0);
    CPA_COMMIT();

    const int arow = (lane & 7) + ((lane >> 3) & 1) * 8;
    const int acol8 = (lane >> 4) * 8;
    const int bnof = (lane & 7) + ((lane >> 4) << 3);
    const int bk8  = ((lane >> 3) & 1) * 8;

    int buf = 0;
    for (int ch = 0; ch < 16; ch++) {
        if (ch < 15) { issue_chunk(ch + 1, buf ^ 1); CPA_COMMIT(); cpa_wait<1>(); }
        else         { cpa_wait<0>(); }
        __syncthreads();

        const uint32_t base = sb + buf * BUFSZ;
        #pragma unroll
        for (int ks = 0; ks < 4; ks++) {
            uint32_t aF[2][2][4];
            #pragma unroll
            for (int mt = 0; mt < 2; mt++) {
                uint32_t ad = base + (wm*32 + mt*16 + arow) * STRB + (ks*16 + acol8) * 2;
                ldsm4(aF[0][mt], ad);
                ldsm4(aF[1][mt], ad + OFF_ALO);
            }
            uint32_t bF[2][4][4];
            #pragma unroll
            for (int np = 0; np < 4; np++) {
                uint32_t bd = base + OFF_BHI + (wn*64 + np*16 + bnof) * STRB + (ks*16 + bk8) * 2;
                ldsm4(bF[0][np], bd);
                ldsm4(bF[1][np], bd + OFF_ALO);
            }
            #pragma unroll
            for (int mt = 0; mt < 2; mt++) {
                #pragma unroll
                for (int nt = 0; nt < 8; nt++) {
                    const uint32_t* bh = &bF[0][nt >> 1][(nt & 1) * 2];
                    const uint32_t* bl = &bF[1][nt >> 1][(nt & 1) * 2];
                    mma16816(acc[mt][nt], aF[0][mt], bh);
                    mma16816(acc[mt][nt], aF[0][mt], bl);
                    mma16816(acc[mt][nt], aF[1][mt], bh);
                }
            }
        }
        __syncthreads();
        buf ^= 1;
    }

    // epilogue
    #pragma unroll
    for (int mt = 0; mt < 2; mt++) {
        #pragma unroll
        for (int hf = 0; hf < 2; hf++) {
            int lr = wm*32 + mt*16 + (lane >> 2) + hf*8;
            int t2 = t0 + lr;
            #pragma unroll
            for (int nt = 0; nt < 8; nt++) {
                int c = n0 + wn*64 + nt*8 + (lane & 3)*2;
                float v0 = acc[mt][nt][hf*2+0] + __ldg(bias + c);
                float v1 = acc[mt][nt][hf*2+1] + __ldg(bias + c + 1);
                if (cfg.mode == 0) {
                    // pre-round to tf32 so attention feeds raw bits to mma
                    v0 = __uint_as_float(f2tf32(v0));
                    v1 = __uint_as_float(f2tf32(v1));
                    int h = c >> 6, d = c & 63;
                    size_t o = (((size_t)(b2*NHD + h) * TT + cfg.toffOut + t2) << 6) + d;
                    *(float2*)(out + o) = make_float2(v0, v1);
                } else {
                    size_t o = (size_t)(m0 + lr) * HD + c;
                    float2 rr = *(const float2*)(cfg.res + o);
                    *(float2*)(out + o) = make_float2(v0 + rr.x, v1 + rr.y);
                }
            }
        }
    }
}

// ---------------- tf32 tensor-core flash attention ----------------
// grid (9, 64); 256 threads = 8 warps; warp w owns rows w*16..w*16+15.
// SMEM: Qs[128][68] f32, Ks x2 [128][68] f32, Vs[128][72] f32, Ps[128][140] f32
#define AT_SQ 68
#define AT_SV 72
#define AT_SP 140
#define AO_K0 34816
#define AO_K1 69632
#define AO_V  104448
#define AO_P  141312
#define ATTN_SMEM 212992

__global__ __launch_bounds__(256) void attn_tc(
    const float* __restrict__ Q, const float* __restrict__ K,
    const float* __restrict__ V, const float* __restrict__ mask,
    float* __restrict__ CTX)
{
    extern __shared__ char smc[];
    float* Qs = (float*)smc;
    float* Vs = (float*)(smc + AO_V);
    uint32_t* Pu = (uint32_t*)(smc + AO_P);
    const uint32_t sbase = smem_u32(smc);

    const int tid = threadIdx.x, wid = tid >> 5, lane = tid & 31;
    const int bh = blockIdx.y, b = bh >> 4, h = bh & 15;
    const int q0 = blockIdx.x * 128;
    const float* Qg = Q + ((size_t)bh * TT + q0) * DHD;
    const float* Kg = K + (size_t)bh * TT * DHD;
    const float* Vg = V + (size_t)bh * TT * DHD;
    const float* mb = mask + (size_t)b * TT;

    // Q tile
    #pragma unroll
    for (int i = 0; i < 8; i++) {
        int idx = tid + i * 256;
        int r = idx >> 4, c = (idx & 15) * 4;
        *(float4*)(Qs + r * AT_SQ + c) = *(const float4*)(Qg + r * DHD + c);
    }

    auto issueK = [&](int ch, int kb){
        uint32_t dst = sbase + (kb ? AO_K1 : AO_K0);
        const float* src = Kg + (size_t)ch * 128 * DHD;
        #pragma unroll
        for (int i = 0; i < 8; i++) {
            int idx = tid + i * 256;
            int r = idx >> 4, s = idx & 15;
            CPA16(dst + r * (AT_SQ*4) + s * 16, src + r * DHD + s * 4);
        }
        CPA_COMMIT();
    };
    auto issueV = [&](int ch){
        const float* src = Vg + (size_t)ch * 128 * DHD;
        #pragma unroll
        for (int i = 0; i < 8; i++) {
            int idx = tid + i * 256;
            int r = idx >> 4, s = idx & 15;
            CPA16(sbase + AO_V + r * (AT_SV*4) + s * 16, src + r * DHD + s * 4);
        }
        CPA_COMMIT();
    };

    issueK(0, 0);
    issueV(0);

    const int r4 = lane >> 2, c4 = lane & 3;
    const int row0 = wid * 16 + r4;

    float O[8][4];
    #pragma unroll
    for (int nt = 0; nt < 8; nt++)
        #pragma unroll
        for (int j = 0; j < 4; j++) O[nt][j] = 0.f;
    float m0 = -1e30f, m1 = -1e30f, l0 = 0.f, l1 = 0.f;

    int buf = 0;
    for (int ch = 0; ch < 9; ch++) {
        if (ch < 8) { issueK(ch + 1, buf ^ 1); cpa_wait<2>(); }
        else        { cpa_wait<1>(); }
        __syncthreads();

        const float* Kb = (const float*)(smc + (buf ? AO_K1 : AO_K0));

        // ---- S = Q @ K^T (tf32) ----
        float S[16][4];
        #pragma unroll
        for (int nt = 0; nt < 16; nt++)
            #pragma unroll
            for (int j = 0; j < 4; j++) S[nt][j] = 0.f;

        #pragma unroll
        for (int ks = 0; ks < 8; ks++) {
            uint32_t a[4];
            a[0] = __float_as_uint(Qs[ row0      * AT_SQ + ks*8 + c4    ]);
            a[1] = __float_as_uint(Qs[(row0 + 8) * AT_SQ + ks*8 + c4    ]);
            a[2] = __float_as_uint(Qs[ row0      * AT_SQ + ks*8 + c4 + 4]);
            a[3] = __float_as_uint(Qs[(row0 + 8) * AT_SQ + ks*8 + c4 + 4]);
            #pragma unroll
            for (int nt = 0; nt < 16; nt++) {
                uint32_t bb[2];
                bb[0] = __float_as_uint(Kb[(nt*8 + r4) * AT_SQ + ks*8 + c4    ]);
                bb[1] = __float_as_uint(Kb[(nt*8 + r4) * AT_SQ + ks*8 + c4 + 4]);
                mma_tf32(S[nt], a, bb);
            }
        }

        // ---- scale + mask + online softmax ----
        const int kgl = ch * 128;
        float mt0 = -1e30f, mt1 = -1e30f;
        #pragma unroll
        for (int nt = 0; nt < 16; nt++) {
            float2 mk = __ldg((const float2*)(mb + kgl + nt*8 + 2*c4));
            S[nt][0] = S[nt][0] * 0.125f + mk.x;
            S[nt][1] = S[nt][1] * 0.125f + mk.y;
            S[nt][2] = S[nt][2] * 0.125f + mk.x;
            S[nt][3] = S[nt][3] * 0.125f + mk.y;
            mt0 = fmaxf(mt0, fmaxf(S[nt][0], S[nt][1]));
            mt1 = fmaxf(mt1, fmaxf(S[nt][2], S[nt][3]));
        }
        mt0 = fmaxf(mt0, __shfl_xor_sync(0xffffffffu, mt0, 1));
        mt0 = fmaxf(mt0, __shfl_xor_sync(0xffffffffu, mt0, 2));
        mt1 = fmaxf(mt1, __shfl_xor_sync(0xffffffffu, mt1, 1));
        mt1 = fmaxf(mt1, __shfl_xor_sync(0xffffffffu, mt1, 2));

        float mn0 = fmaxf(m0, mt0), mn1 = fmaxf(m1, mt1);
        float al0 = __expf(m0 - mn0), al1 = __expf(m1 - mn1);
        #pragma unroll
        for (int nt = 0; nt < 8; nt++) {
            O[nt][0] *= al0; O[nt][1] *= al0;
            O[nt][2] *= al1; O[nt][3] *= al1;
        }

        float ls0 = 0.f, ls1 = 0.f;
        #pragma unroll
        for (int nt = 0; nt < 16; nt++) {
            float p00 = __expf(S[nt][0] - mn0);
            float p01 = __expf(S[nt][1] - mn0);
            float p10 = __expf(S[nt][2] - mn1);
            float p11 = __expf(S[nt][3] - mn1);
            ls0 += p00 + p01;
            ls1 += p10 + p11;
            int cw = nt*8 + 2*c4;
            Pu[ row0      * AT_SP + cw    ] = f2tf32(p00);
            Pu[ row0      * AT_SP + cw + 1] = f2tf32(p01);
            Pu[(row0 + 8) * AT_SP + cw    ] = f2tf32(p10);
            Pu[(row0 + 8) * AT_SP + cw + 1] = f2tf32(p11);
        }
        ls0 += __shfl_xor_sync(0xffffffffu, ls0, 1);
        ls0 += __shfl_xor_sync(0xffffffffu, ls0, 2);
        ls1 += __shfl_xor_sync(0xffffffffu, ls1, 1);
        ls1 += __shfl_xor_sync(0xffffffffu, ls1, 2);
        l0 = l0 * al0 + ls0; m0 = mn0;
        l1 = l1 * al1 + ls1; m1 = mn1;

        // V ready + P visible
        if (ch < 8) cpa_wait<1>(); else cpa_wait<0>();
        __syncthreads();

        // ---- O += P @ V (tf32) ----
        #pragma unroll
        for (int ks = 0; ks < 16; ks++) {
            uint32_t a[4];
            a[0] = Pu[ row0      * AT_SP + ks*8 + c4    ];
            a[1] = Pu[(row0 + 8) * AT_SP + ks*8 + c4    ];
            a[2] = Pu[ row0      * AT_SP + ks*8 + c4 + 4];
            a[3] = Pu[(row0 + 8) * AT_SP + ks*8 + c4 + 4];
            #pragma unroll
            for (int nt = 0; nt < 8; nt++) {
                uint32_t bb[2];
                bb[0] = __float_as_uint(Vs[(ks*8 + c4    ) * AT_SV + nt*8 + r4]);
                bb[1] = __float_as_uint(Vs[(ks*8 + c4 + 4) * AT_SV + nt*8 + r4]);
                mma_tf32(O[nt], a, bb);
            }
        }
        __syncthreads();
        if (ch < 8) issueV(ch + 1);
        buf ^= 1;
    }

    float i0 = 1.f / l0, i1 = 1.f / l1;
    #pragma unroll
    for (int nt = 0; nt < 8; nt++) {
        int c = h * 64 + nt*8 + 2*c4;
        size_t o0 = (size_t)(b * TT + q0 + row0) * HD + c;
        size_t o1 = (size_t)(b * TT + q0 + row0 + 8) * HD + c;
        *(float2*)(CTX + o0) = make_float2(O[nt][0] * i0, O[nt][1] * i0);
        *(float2*)(CTX + o1) = make_float2(O[nt][2] * i1, O[nt][3] * i1);
    }
}

// ---------------- layernorm ----------------
__device__ __forceinline__ float block_sum(float v, float* sh) {
    #pragma unroll
    for (int o = 16; o; o >>= 1) v += __shfl_xor_sync(0xffffffffu, v, o);
    int tid = threadIdx.x;
    if ((tid & 31) == 0) sh[tid >> 5] = v;
    __syncthreads();
    if (tid < 32) {
        float t = (tid < 8) ? sh[tid] : 0.f;
        #pragma unroll
        for (int o = 4; o; o >>= 1) t += __shfl_xor_sync(0xffffffffu, t, o);
        if (tid == 0) sh[0] = t;
    }
    __syncthreads();
    float r = sh[0];
    __syncthreads();
    return r;
}

__global__ __launch_bounds__(256) void ln_kernel(
    const float* __restrict__ Y, const float* __restrict__ g,
    const float* __restrict__ bt, float* __restrict__ out)
{
    __shared__ float sh[8];
    int row = blockIdx.x, tid = threadIdx.x;
    float4 v = ((const float4*)(Y + (size_t)row * HD))[tid];
    float mu = block_sum(v.x + v.y + v.z + v.w, sh) * (1.f / HD);
    float4 d = make_float4(v.x - mu, v.y - mu, v.z - mu, v.w - mu);
    float var = block_sum(d.x*d.x + d.y*d.y + d.z*d.z + d.w*d.w, sh) * (1.f / HD);
    float rs = rsqrtf(var + 1e-12f);
    float4 gg = ((const float4*)g)[tid];
    float4 bb = ((const float4*)bt)[tid];
    ((float4*)(out + (size_t)row * HD))[tid] =
        make_float4(d.x*rs*gg.x + bb.x, d.y*rs*gg.y + bb.y, d.z*rs*gg.z + bb.z, d.w*rs*gg.w + bb.w);
}

// ---------------- launch ----------------
extern "C" void kernel_launch(void* const* d_in, const int* in_sizes, int n_in,
                              void* d_out, int out_size)
{
    (void)in_sizes; (void)n_in; (void)out_size;
    const float* word = (const float*)d_in[0];
    const float* ent  = (const float*)d_in[1];
    const float* mask = (const float*)d_in[2];
    const float* qpos = (const float*)d_in[3];
    const float* Wq  = (const float*)d_in[4];   const float* bq  = (const float*)d_in[5];
    const float* Wk  = (const float*)d_in[6];   const float* bk  = (const float*)d_in[7];
    const float* Wv  = (const float*)d_in[8];   const float* bv  = (const float*)d_in[9];
    const float* Weq = (const float*)d_in[10];  const float* beq = (const float*)d_in[11];
    const float* Wek = (const float*)d_in[12];  const float* bek = (const float*)d_in[13];
    const float* Wev = (const float*)d_in[14];  const float* bev = (const float*)d_in[15];
    const float* Wo  = (const float*)d_in[16];  const float* bo  = (const float*)d_in[17];
    const float* Weo = (const float*)d_in[18];  const float* beo = (const float*)d_in[19];
    const float* lng  = (const float*)d_in[20]; const float* lnb  = (const float*)d_in[21];
    const float* elng = (const float*)d_in[22]; const float* elnb = (const float*)d_in[23];
    float* out = (float*)d_out;

    float *Q, *K, *V, *CTX;
    __nv_bfloat16 *XHi, *XLo, *WtHi, *WtLo;
    cudaGetSymbolAddress((void**)&Q,    g_Q);
    cudaGetSymbolAddress((void**)&K,    g_K);
    cudaGetSymbolAddress((void**)&V,    g_V);
    cudaGetSymbolAddress((void**)&CTX,  g_CTX);
    cudaGetSymbolAddress((void**)&XHi,  g_XHi);
    cudaGetSymbolAddress((void**)&XLo,  g_XLo);
    cudaGetSymbolAddress((void**)&WtHi, g_WtHi);
    cudaGetSymbolAddress((void**)&WtLo, g_WtLo);

    cudaFuncSetAttribute(gemm_mma, cudaFuncAttributeMaxDynamicSharedMemorySize, SMEM_GEMM);
    cudaFuncSetAttribute(attn_tc, cudaFuncAttributeMaxDynamicSharedMemorySize, ATTN_SMEM);

    // 0. weight prep
    W8 w8; w8.p[0]=Wq; w8.p[1]=Wk; w8.p[2]=Wv; w8.p[3]=Weq; w8.p[4]=Wek; w8.p[5]=Wev; w8.p[6]=Wo; w8.p[7]=Weo;
    wprep_kernel<<<dim3(32, 32, 8), 256>>>(w8, WtHi, WtLo);

    // 1. activation prep
    xprep_kernel <<<(NB*TW*HD/4)/256, 256>>>(word, XHi, XLo);
    pexprep_kernel<<<(NB*TE*HD/4)/256, 256>>>(ent, qpos, XHi + (size_t)4096*HD, XLo + (size_t)4096*HD);
    xprep_kernel <<<(NB*TE*HD/4)/256, 256>>>(ent, XHi + (size_t)4608*HD, XLo + (size_t)4608*HD);

    // 2. projections
    GemmCfg c1 = {};
    c1.b0 = bq; c1.b1 = bk; c1.b2 = bv;
    c1.o0 = Q; c1.o1 = K; c1.o2 = V;
    c1.widx0 = 0; c1.Tseg = TW; c1.Tfull = TW; c1.toff = 0; c1.mode = 0; c1.toffOut = 0;
    c1.xbase01 = 0; c1.xbase2 = 0;
    gemm_mma<<<dim3(8, (NB*TW)/128, 3), 256, SMEM_GEMM>>>(XHi, XLo, WtHi, WtLo, c1);

    GemmCfg c2 = {};
    c2.b0 = beq; c2.b1 = bek; c2.b2 = bev;
    c2.o0 = Q; c2.o1 = K; c2.o2 = V;
    c2.widx0 = 3; c2.Tseg = TE; c2.Tfull = TE; c2.toff = 0; c2.mode = 0; c2.toffOut = TW;
    c2.xbase01 = 4096; c2.xbase2 = 4608;
    gemm_mma<<<dim3(8, (NB*TE)/128, 3), 256, SMEM_GEMM>>>(XHi, XLo, WtHi, WtLo, c2);

    // 3. attention (tf32 tensor cores)
    attn_tc<<<dim3(TT/128, NB*NHD), 256, ATTN_SMEM>>>(Q, K, V, mask, CTX);

    // 4. CTX prep + output projections
    xprep_kernel<<<(NB*TT*HD/4)/256, 256>>>(CTX, XHi, XLo);

    GemmCfg c3 = {};
    c3.b0 = bo; c3.o0 = Q; c3.res = word;
    c3.widx0 = 6; c3.Tseg = TW; c3.Tfull = TT; c3.toff = 0; c3.mode = 1;
    c3.xbase01 = 0; c3.xbase2 = 0;
    gemm_mma<<<dim3(8, (NB*TW)/128, 1), 256, SMEM_GEMM>>>(XHi, XLo, WtHi, WtLo, c3);

    GemmCfg c4 = {};
    c4.b0 = beo; c4.o0 = K; c4.res = ent;
    c4.widx0 = 7; c4.Tseg = TE; c4.Tfull = TT; c4.toff = TW; c4.mode = 1;
    c4.xbase01 = 0; c4.xbase2 = 0;
    gemm_mma<<<dim3(8, (NB*TE)/128, 1), 256, SMEM_GEMM>>>(XHi, XLo, WtHi, WtLo, c4);

    // 5. layernorm
    ln_kernel<<<NB * TW, 256>>>(Q, lng, lnb, out);
    ln_kernel<<<NB * TE, 256>>>(K, elng, elnb, out + (size_t)NB * TW * HD);
}

// round 5
// speedup vs baseline: 6.4533x; 1.5717x over previous
#include <cuda_runtime.h>
#include <cuda_bf16.h>
#include <cuda_fp16.h>
#include <stdint.h>
#include <math.h>

#define NB  4
#define TW  1024
#define TE  128
#define TT  1152
#define HD  1024
#define NHD 16
#define DHD 64

// ---------------- scratch ----------------
__device__ float g_Q  [NB*NHD*TT*DHD];     // fp32 q-proj; reused as word-Y temp
__device__ float g_K  [NB*NHD*TT*DHD];     // fp32 k-proj; reused as ent-Y temp
__device__ float g_V  [NB*NHD*TT*DHD];
__device__ float g_CTX[NB*TT*HD];
// fp16 prepped activations: rows 0..4095 word (later CTX 0..4607), 4096..4607 pos_ent, 4608..5119 ent
__device__ __half g_Xh[5120*1024];
__device__ __half g_Wt[8*1024*1024];       // 8 weights, transposed [N,K], fp16

// ---------------- helpers ----------------
__device__ __forceinline__ uint32_t smem_u32(const void* p){
    uint32_t a;
    asm("{ .reg .u64 t; cvta.to.shared.u64 t, %1; cvt.u32.u64 %0, t; }" : "=r"(a) : "l"(p));
    return a;
}
__device__ __forceinline__ uint32_t f2tf32(float f){
    uint32_t u; asm("cvt.rna.tf32.f32 %0, %1;" : "=r"(u) : "f"(f)); return u;
}
__device__ __forceinline__ uint32_t pkh(float a, float b){
    __half2 h = __floats2half2_rn(a, b);
    return *reinterpret_cast<uint32_t*>(&h);
}

#define CPA16(dst, src) asm volatile("cp.async.cg.shared.global [%0], [%1], 16;" :: "r"(dst), "l"(src))
#define CPA_COMMIT()    asm volatile("cp.async.commit_group;" ::: "memory")
template<int N> __device__ __forceinline__ void cpa_wait(){
    asm volatile("cp.async.wait_group %0;" :: "n"(N) : "memory");
}

__device__ __forceinline__ void ldsm4(uint32_t* r, uint32_t addr){
    asm volatile("ldmatrix.sync.aligned.m8n8.x4.shared.b16 {%0,%1,%2,%3}, [%4];"
        : "=r"(r[0]), "=r"(r[1]), "=r"(r[2]), "=r"(r[3]) : "r"(addr));
}
__device__ __forceinline__ void mma16816h(float* d, const uint32_t* a, const uint32_t* b){
    asm volatile("mma.sync.aligned.m16n8k16.row.col.f32.f16.f16.f32 "
        "{%0,%1,%2,%3}, {%4,%5,%6,%7}, {%8,%9}, {%0,%1,%2,%3};"
        : "+f"(d[0]), "+f"(d[1]), "+f"(d[2]), "+f"(d[3])
        : "r"(a[0]), "r"(a[1]), "r"(a[2]), "r"(a[3]), "r"(b[0]), "r"(b[1]));
}
__device__ __forceinline__ void mma_tf32(float* d, const uint32_t* a, const uint32_t* b){
    asm volatile("mma.sync.aligned.m16n8k8.row.col.f32.tf32.tf32.f32 "
        "{%0,%1,%2,%3}, {%4,%5,%6,%7}, {%8,%9}, {%0,%1,%2,%3};"
        : "+f"(d[0]), "+f"(d[1]), "+f"(d[2]), "+f"(d[3])
        : "r"(a[0]), "r"(a[1]), "r"(a[2]), "r"(a[3]), "r"(b[0]), "r"(b[1]));
}

// ---------------- weight prep: transpose + fp16 ----------------
struct W8 { const float* p[8]; };

__global__ __launch_bounds__(256) void wprep_kernel(W8 ws, __half* outW){
    __shared__ float tile[32][33];
    const float* W = ws.p[blockIdx.z];
    int n0 = blockIdx.x * 32, k0 = blockIdx.y * 32;
    int tx = threadIdx.x & 31, ty = threadIdx.x >> 5;
    #pragma unroll
    for (int i = 0; i < 32; i += 8)
        tile[ty + i][tx] = W[(size_t)(k0 + ty + i) * 1024 + n0 + tx];
    __syncthreads();
    #pragma unroll
    for (int i = 0; i < 32; i += 8) {
        float f = tile[tx][ty + i];
        size_t o = ((size_t)blockIdx.z << 20) + ((size_t)(n0 + ty + i) << 10) + k0 + tx;
        outW[o] = __float2half_rn(f);
    }
}

// ---------------- activation prep (fp32 -> fp16) ----------------
__global__ void xprep_kernel(const float* __restrict__ X, __half* __restrict__ o){
    size_t i = (size_t)blockIdx.x * blockDim.x + threadIdx.x;
    float4 v = ((const float4*)X)[i];
    ((uint2*)o)[i] = make_uint2(pkh(v.x, v.y), pkh(v.z, v.w));
}

__global__ void pexprep_kernel(const float* __restrict__ ent, const float* __restrict__ qp,
                               __half* __restrict__ o){
    size_t i = (size_t)blockIdx.x * blockDim.x + threadIdx.x;
    float4 a = ((const float4*)ent)[i];
    float4 b = ((const float4*)qp)[i];
    ((uint2*)o)[i] = make_uint2(pkh((a.x+b.x)*0.5f, (a.y+b.y)*0.5f),
                                pkh((a.z+b.z)*0.5f, (a.w+b.w)*0.5f));
}

// ---------------- fp16 HMMA GEMM ----------------
// C[M,1024] = X[M,1024] @ W[1024,1024], fp16 in, fp32 accumulate.
// CTA: 128(M) x 128(N); K chunks of 64, cp.async double buffered; 2 CTAs/SM.
#define STRB  144            // 72 fp16 * 2B
#define OFF_B 18432
#define BUFSZ 36864
#define SMEM_GEMM (2*BUFSZ)  // 73728

struct GemmCfg {
    const float* b0; const float* b1; const float* b2;
    float* o0; float* o1; float* o2;
    const float* res;
    int widx0, Tseg, Tfull, toff, mode, toffOut;
    int xbase01, xbase2;
};

__global__ __launch_bounds__(256, 2) void gemm_mma(
    const __half* __restrict__ Xh, const __half* __restrict__ WtAll, GemmCfg cfg)
{
    extern __shared__ char smc[];
    const uint32_t sb = smem_u32(smc);
    const int tid = threadIdx.x;
    const int wid = tid >> 5, lane = tid & 31;
    const int wm = wid >> 1, wn = wid & 1;
    const int z = blockIdx.z;

    const float* bias = (z == 0) ? cfg.b0 : (z == 1) ? cfg.b1 : cfg.b2;
    float* out        = (z == 0) ? cfg.o0 : (z == 1) ? cfg.o1 : cfg.o2;
    const __half* Wt = WtAll + ((size_t)(cfg.widx0 + z) << 20);

    const int m0 = blockIdx.y * 128;
    const int n0 = blockIdx.x * 128;
    const int b2 = m0 / cfg.Tseg;
    const int t0 = m0 - b2 * cfg.Tseg;
    const int xbase = (z == 2) ? cfg.xbase2 : cfg.xbase01;
    const __half* Ah = Xh + ((size_t)xbase + (size_t)b2 * cfg.Tfull + cfg.toff + t0) * HD;

    float acc[2][8][4];
    #pragma unroll
    for (int mt = 0; mt < 2; mt++)
        #pragma unroll
        for (int nt = 0; nt < 8; nt++)
            #pragma unroll
            for (int j = 0; j < 4; j++) acc[mt][nt][j] = 0.f;

    auto issue_chunk = [&](int ch, int buf){
        const int k0 = ch * 64;
        const uint32_t base = sb + buf * BUFSZ;
        #pragma unroll
        for (int i = 0; i < 4; i++) {
            int q = tid + i * 256;
            int r = q >> 3, s8 = q & 7;
            CPA16(base + r * STRB + s8 * 16,        Ah + (size_t)r * HD + k0 + s8 * 8);
            CPA16(base + OFF_B + r * STRB + s8 * 16, Wt + (size_t)(n0 + r) * HD + k0 + s8 * 8);
        }
    };

    issue_chunk(0, 0);
    CPA_COMMIT();

    const int arow = (lane & 7) + ((lane >> 3) & 1) * 8;
    const int acol8 = (lane >> 4) * 8;
    const int bnof = (lane & 7) + ((lane >> 4) << 3);
    const int bk8  = ((lane >> 3) & 1) * 8;

    int buf = 0;
    for (int ch = 0; ch < 16; ch++) {
        if (ch < 15) { issue_chunk(ch + 1, buf ^ 1); CPA_COMMIT(); cpa_wait<1>(); }
        else         { cpa_wait<0>(); }
        __syncthreads();

        const uint32_t base = sb + buf * BUFSZ;
        #pragma unroll
        for (int ks = 0; ks < 4; ks++) {
            uint32_t aF[2][4];
            #pragma unroll
            for (int mt = 0; mt < 2; mt++)
                ldsm4(aF[mt], base + (wm*32 + mt*16 + arow) * STRB + (ks*16 + acol8) * 2);
            uint32_t bF[4][4];
            #pragma unroll
            for (int np = 0; np < 4; np++)
                ldsm4(bF[np], base + OFF_B + (wn*64 + np*16 + bnof) * STRB + (ks*16 + bk8) * 2);
            #pragma unroll
            for (int mt = 0; mt < 2; mt++)
                #pragma unroll
                for (int nt = 0; nt < 8; nt++)
                    mma16816h(acc[mt][nt], aF[mt], &bF[nt >> 1][(nt & 1) * 2]);
        }
        __syncthreads();
        buf ^= 1;
    }

    // epilogue
    #pragma unroll
    for (int mt = 0; mt < 2; mt++) {
        #pragma unroll
        for (int hf = 0; hf < 2; hf++) {
            int lr = wm*32 + mt*16 + (lane >> 2) + hf*8;
            int t2 = t0 + lr;
            #pragma unroll
            for (int nt = 0; nt < 8; nt++) {
                int c = n0 + wn*64 + nt*8 + (lane & 3)*2;
                float v0 = acc[mt][nt][hf*2+0] + __ldg(bias + c);
                float v1 = acc[mt][nt][hf*2+1] + __ldg(bias + c + 1);
                if (cfg.mode == 0) {
                    v0 = __uint_as_float(f2tf32(v0));
                    v1 = __uint_as_float(f2tf32(v1));
                    int h = c >> 6, d = c & 63;
                    size_t o = (((size_t)(b2*NHD + h) * TT + cfg.toffOut + t2) << 6) + d;
                    *(float2*)(out + o) = make_float2(v0, v1);
                } else {
                    size_t o = (size_t)(m0 + lr) * HD + c;
                    float2 rr = *(const float2*)(cfg.res + o);
                    *(float2*)(out + o) = make_float2(v0 + rr.x, v1 + rr.y);
                }
            }
        }
    }
}

// ---------------- tf32 tensor-core flash attention ----------------
#define AT_SQ 68
#define AT_SV 72
#define AT_SP 140
#define AO_K0 34816
#define AO_K1 69632
#define AO_V  104448
#define AO_P  141312
#define ATTN_SMEM 212992

__global__ __launch_bounds__(256) void attn_tc(
    const float* __restrict__ Q, const float* __restrict__ K,
    const float* __restrict__ V, const float* __restrict__ mask,
    float* __restrict__ CTX)
{
    extern __shared__ char smc[];
    float* Qs = (float*)smc;
    float* Vs = (float*)(smc + AO_V);
    uint32_t* Pu = (uint32_t*)(smc + AO_P);
    const uint32_t sbase = smem_u32(smc);

    const int tid = threadIdx.x, wid = tid >> 5, lane = tid & 31;
    const int bh = blockIdx.y, b = bh >> 4, h = bh & 15;
    const int q0 = blockIdx.x * 128;
    const float* Qg = Q + ((size_t)bh * TT + q0) * DHD;
    const float* Kg = K + (size_t)bh * TT * DHD;
    const float* Vg = V + (size_t)bh * TT * DHD;
    const float* mb = mask + (size_t)b * TT;

    #pragma unroll
    for (int i = 0; i < 8; i++) {
        int idx = tid + i * 256;
        int r = idx >> 4, c = (idx & 15) * 4;
        *(float4*)(Qs + r * AT_SQ + c) = *(const float4*)(Qg + r * DHD + c);
    }

    auto issueK = [&](int ch, int kb){
        uint32_t dst = sbase + (kb ? AO_K1 : AO_K0);
        const float* src = Kg + (size_t)ch * 128 * DHD;
        #pragma unroll
        for (int i = 0; i < 8; i++) {
            int idx = tid + i * 256;
            int r = idx >> 4, s = idx & 15;
            CPA16(dst + r * (AT_SQ*4) + s * 16, src + r * DHD + s * 4);
        }
        CPA_COMMIT();
    };
    auto issueV = [&](int ch){
        const float* src = Vg + (size_t)ch * 128 * DHD;
        #pragma unroll
        for (int i = 0; i < 8; i++) {
            int idx = tid + i * 256;
            int r = idx >> 4, s = idx & 15;
            CPA16(sbase + AO_V + r * (AT_SV*4) + s * 16, src + r * DHD + s * 4);
        }
        CPA_COMMIT();
    };

    issueK(0, 0);
    issueV(0);

    const int r4 = lane >> 2, c4 = lane & 3;
    const int row0 = wid * 16 + r4;

    float O[8][4];
    #pragma unroll
    for (int nt = 0; nt < 8; nt++)
        #pragma unroll
        for (int j = 0; j < 4; j++) O[nt][j] = 0.f;
    float m0 = -1e30f, m1 = -1e30f, l0 = 0.f, l1 = 0.f;

    int buf = 0;
    for (int ch = 0; ch < 9; ch++) {
        if (ch < 8) { issueK(ch + 1, buf ^ 1); cpa_wait<2>(); }
        else        { cpa_wait<1>(); }
        __syncthreads();

        const float* Kb = (const float*)(smc + (buf ? AO_K1 : AO_K0));

        float S[16][4];
        #pragma unroll
        for (int nt = 0; nt < 16; nt++)
            #pragma unroll
            for (int j = 0; j < 4; j++) S[nt][j] = 0.f;

        #pragma unroll
        for (int ks = 0; ks < 8; ks++) {
            uint32_t a[4];
            a[0] = __float_as_uint(Qs[ row0      * AT_SQ + ks*8 + c4    ]);
            a[1] = __float_as_uint(Qs[(row0 + 8) * AT_SQ + ks*8 + c4    ]);
            a[2] = __float_as_uint(Qs[ row0      * AT_SQ + ks*8 + c4 + 4]);
            a[3] = __float_as_uint(Qs[(row0 + 8) * AT_SQ + ks*8 + c4 + 4]);
            #pragma unroll
            for (int nt = 0; nt < 16; nt++) {
                uint32_t bb[2];
                bb[0] = __float_as_uint(Kb[(nt*8 + r4) * AT_SQ + ks*8 + c4    ]);
                bb[1] = __float_as_uint(Kb[(nt*8 + r4) * AT_SQ + ks*8 + c4 + 4]);
                mma_tf32(S[nt], a, bb);
            }
        }

        const int kgl = ch * 128;
        float mt0 = -1e30f, mt1 = -1e30f;
        #pragma unroll
        for (int nt = 0; nt < 16; nt++) {
            float2 mk = __ldg((const float2*)(mb + kgl + nt*8 + 2*c4));
            S[nt][0] = S[nt][0] * 0.125f + mk.x;
            S[nt][1] = S[nt][1] * 0.125f + mk.y;
            S[nt][2] = S[nt][2] * 0.125f + mk.x;
            S[nt][3] = S[nt][3] * 0.125f + mk.y;
            mt0 = fmaxf(mt0, fmaxf(S[nt][0], S[nt][1]));
            mt1 = fmaxf(mt1, fmaxf(S[nt][2], S[nt][3]));
        }
        mt0 = fmaxf(mt0, __shfl_xor_sync(0xffffffffu, mt0, 1));
        mt0 = fmaxf(mt0, __shfl_xor_sync(0xffffffffu, mt0, 2));
        mt1 = fmaxf(mt1, __shfl_xor_sync(0xffffffffu, mt1, 1));
        mt1 = fmaxf(mt1, __shfl_xor_sync(0xffffffffu, mt1, 2));

        float mn0 = fmaxf(m0, mt0), mn1 = fmaxf(m1, mt1);
        float al0 = __expf(m0 - mn0), al1 = __expf(m1 - mn1);
        #pragma unroll
        for (int nt = 0; nt < 8; nt++) {
            O[nt][0] *= al0; O[nt][1] *= al0;
            O[nt][2] *= al1; O[nt][3] *= al1;
        }

        float ls0 = 0.f, ls1 = 0.f;
        #pragma unroll
        for (int nt = 0; nt < 16; nt++) {
            float p00 = __expf(S[nt][0] - mn0);
            float p01 = __expf(S[nt][1] - mn0);
            float p10 = __expf(S[nt][2] - mn1);
            float p11 = __expf(S[nt][3] - mn1);
            ls0 += p00 + p01;
            ls1 += p10 + p11;
            int cw = nt*8 + 2*c4;
            Pu[ row0      * AT_SP + cw    ] = f2tf32(p00);
            Pu[ row0      * AT_SP + cw + 1] = f2tf32(p01);
            Pu[(row0 + 8) * AT_SP + cw    ] = f2tf32(p10);
            Pu[(row0 + 8) * AT_SP + cw + 1] = f2tf32(p11);
        }
        ls0 += __shfl_xor_sync(0xffffffffu, ls0, 1);
        ls0 += __shfl_xor_sync(0xffffffffu, ls0, 2);
        ls1 += __shfl_xor_sync(0xffffffffu, ls1, 1);
        ls1 += __shfl_xor_sync(0xffffffffu, ls1, 2);
        l0 = l0 * al0 + ls0; m0 = mn0;
        l1 = l1 * al1 + ls1; m1 = mn1;

        if (ch < 8) cpa_wait<1>(); else cpa_wait<0>();
        __syncthreads();

        #pragma unroll
        for (int ks = 0; ks < 16; ks++) {
            uint32_t a[4];
            a[0] = Pu[ row0      * AT_SP + ks*8 + c4    ];
            a[1] = Pu[(row0 + 8) * AT_SP + ks*8 + c4    ];
            a[2] = Pu[ row0      * AT_SP + ks*8 + c4 + 4];
            a[3] = Pu[(row0 + 8) * AT_SP + ks*8 + c4 + 4];
            #pragma unroll
            for (int nt = 0; nt < 8; nt++) {
                uint32_t bb[2];
                bb[0] = __float_as_uint(Vs[(ks*8 + c4    ) * AT_SV + nt*8 + r4]);
                bb[1] = __float_as_uint(Vs[(ks*8 + c4 + 4) * AT_SV + nt*8 + r4]);
                mma_tf32(O[nt], a, bb);
            }
        }
        __syncthreads();
        if (ch < 8) issueV(ch + 1);
        buf ^= 1;
    }

    float i0 = 1.f / l0, i1 = 1.f / l1;
    #pragma unroll
    for (int nt = 0; nt < 8; nt++) {
        int c = h * 64 + nt*8 + 2*c4;
        size_t o0 = (size_t)(b * TT + q0 + row0) * HD + c;
        size_t o1 = (size_t)(b * TT + q0 + row0 + 8) * HD + c;
        *(float2*)(CTX + o0) = make_float2(O[nt][0] * i0, O[nt][1] * i0);
        *(float2*)(CTX + o1) = make_float2(O[nt][2] * i1, O[nt][3] * i1);
    }
}

// ---------------- layernorm ----------------
__device__ __forceinline__ float block_sum(float v, float* sh) {
    #pragma unroll
    for (int o = 16; o; o >>= 1) v += __shfl_xor_sync(0xffffffffu, v, o);
    int tid = threadIdx.x;
    if ((tid & 31) == 0) sh[tid >> 5] = v;
    __syncthreads();
    if (tid < 32) {
        float t = (tid < 8) ? sh[tid] : 0.f;
        #pragma unroll
        for (int o = 4; o; o >>= 1) t += __shfl_xor_sync(0xffffffffu, t, o);
        if (tid == 0) sh[0] = t;
    }
    __syncthreads();
    float r = sh[0];
    __syncthreads();
    return r;
}

__global__ __launch_bounds__(256) void ln_kernel(
    const float* __restrict__ Y, const float* __restrict__ g,
    const float* __restrict__ bt, float* __restrict__ out)
{
    __shared__ float sh[8];
    int row = blockIdx.x, tid = threadIdx.x;
    float4 v = ((const float4*)(Y + (size_t)row * HD))[tid];
    float mu = block_sum(v.x + v.y + v.z + v.w, sh) * (1.f / HD);
    float4 d = make_float4(v.x - mu, v.y - mu, v.z - mu, v.w - mu);
    float var = block_sum(d.x*d.x + d.y*d.y + d.z*d.z + d.w*d.w, sh) * (1.f / HD);
    float rs = rsqrtf(var + 1e-12f);
    float4 gg = ((const float4*)g)[tid];
    float4 bb = ((const float4*)bt)[tid];
    ((float4*)(out + (size_t)row * HD))[tid] =
        make_float4(d.x*rs*gg.x + bb.x, d.y*rs*gg.y + bb.y, d.z*rs*gg.z + bb.z, d.w*rs*gg.w + bb.w);
}

// ---------------- launch ----------------
extern "C" void kernel_launch(void* const* d_in, const int* in_sizes, int n_in,
                              void* d_out, int out_size)
{
    (void)in_sizes; (void)n_in; (void)out_size;
    const float* word = (const float*)d_in[0];
    const float* ent  = (const float*)d_in[1];
    const float* mask = (const float*)d_in[2];
    const float* qpos = (const float*)d_in[3];
    const float* Wq  = (const float*)d_in[4];   const float* bq  = (const float*)d_in[5];
    const float* Wk  = (const float*)d_in[6];   const float* bk  = (const float*)d_in[7];
    const float* Wv  = (const float*)d_in[8];   const float* bv  = (const float*)d_in[9];
    const float* Weq = (const float*)d_in[10];  const float* beq = (const float*)d_in[11];
    const float* Wek = (const float*)d_in[12];  const float* bek = (const float*)d_in[13];
    const float* Wev = (const float*)d_in[14];  const float* bev = (const float*)d_in[15];
    const float* Wo  = (const float*)d_in[16];  const float* bo  = (const float*)d_in[17];
    const float* Weo = (const float*)d_in[18];  const float* beo = (const float*)d_in[19];
    const float* lng  = (const float*)d_in[20]; const float* lnb  = (const float*)d_in[21];
    const float* elng = (const float*)d_in[22]; const float* elnb = (const float*)d_in[23];
    float* out = (float*)d_out;

    float *Q, *K, *V, *CTX;
    __half *Xh, *Wt;
    cudaGetSymbolAddress((void**)&Q,   g_Q);
    cudaGetSymbolAddress((void**)&K,   g_K);
    cudaGetSymbolAddress((void**)&V,   g_V);
    cudaGetSymbolAddress((void**)&CTX, g_CTX);
    cudaGetSymbolAddress((void**)&Xh,  g_Xh);
    cudaGetSymbolAddress((void**)&Wt,  g_Wt);

    cudaFuncSetAttribute(gemm_mma, cudaFuncAttributeMaxDynamicSharedMemorySize, SMEM_GEMM);
    cudaFuncSetAttribute(attn_tc, cudaFuncAttributeMaxDynamicSharedMemorySize, ATTN_SMEM);

    // 0. weight prep
    W8 w8; w8.p[0]=Wq; w8.p[1]=Wk; w8.p[2]=Wv; w8.p[3]=Weq; w8.p[4]=Wek; w8.p[5]=Wev; w8.p[6]=Wo; w8.p[7]=Weo;
    wprep_kernel<<<dim3(32, 32, 8), 256>>>(w8, Wt);

    // 1. activation prep
    xprep_kernel <<<(NB*TW*HD/4)/256, 256>>>(word, Xh);
    pexprep_kernel<<<(NB*TE*HD/4)/256, 256>>>(ent, qpos, Xh + (size_t)4096*HD);
    xprep_kernel <<<(NB*TE*HD/4)/256, 256>>>(ent, Xh + (size_t)4608*HD);

    // 2. projections
    GemmCfg c1 = {};
    c1.b0 = bq; c1.b1 = bk; c1.b2 = bv;
    c1.o0 = Q; c1.o1 = K; c1.o2 = V;
    c1.widx0 = 0; c1.Tseg = TW; c1.Tfull = TW; c1.toff = 0; c1.mode = 0; c1.toffOut = 0;
    c1.xbase01 = 0; c1.xbase2 = 0;
    gemm_mma<<<dim3(8, (NB*TW)/128, 3), 256, SMEM_GEMM>>>(Xh, Wt, c1);

    GemmCfg c2 = {};
    c2.b0 = beq; c2.b1 = bek; c2.b2 = bev;
    c2.o0 = Q; c2.o1 = K; c2.o2 = V;
    c2.widx0 = 3; c2.Tseg = TE; c2.Tfull = TE; c2.toff = 0; c2.mode = 0; c2.toffOut = TW;
    c2.xbase01 = 4096; c2.xbase2 = 4608;
    gemm_mma<<<dim3(8, (NB*TE)/128, 3), 256, SMEM_GEMM>>>(Xh, Wt, c2);

    // 3. attention (tf32)
    attn_tc<<<dim3(TT/128, NB*NHD), 256, ATTN_SMEM>>>(Q, K, V, mask, CTX);

    // 4. CTX prep + output projections
    xprep_kernel<<<(NB*TT*HD/4)/256, 256>>>(CTX, Xh);

    GemmCfg c3 = {};
    c3.b0 = bo; c3.o0 = Q; c3.res = word;
    c3.widx0 = 6; c3.Tseg = TW; c3.Tfull = TT; c3.toff = 0; c3.mode = 1;
    c3.xbase01 = 0; c3.xbase2 = 0;
    gemm_mma<<<dim3(8, (NB*TW)/128, 1), 256, SMEM_GEMM>>>(Xh, Wt, c3);

    GemmCfg c4 = {};
    c4.b0 = beo; c4.o0 = K; c4.res = ent;
    c4.widx0 = 7; c4.Tseg = TE; c4.Tfull = TT; c4.toff = TW; c4.mode = 1;
    c4.xbase01 = 0; c4.xbase2 = 0;
    gemm_mma<<<dim3(8, (NB*TE)/128, 1), 256, SMEM_GEMM>>>(Xh, Wt, c4);

    // 5. layernorm
    ln_kernel<<<NB * TW, 256>>>(Q, lng, lnb, out);
    ln_kernel<<<NB * TE, 256>>>(K, elng, elnb, out + (size_t)NB * TW * HD);
}

// round 6
// speedup vs baseline: 8.7564x; 1.3569x over previous
#include <cuda_runtime.h>
#include <cuda_bf16.h>
#include <cuda_fp16.h>
#include <stdint.h>
#include <math.h>

#define NB  4
#define TW  1024
#define TE  128
#define TT  1152
#define HD  1024
#define NHD 16
#define DHD 64

// ---------------- scratch ----------------
__device__ float g_Yw [NB*TW*HD];          // word pre-LN temp
__device__ float g_Ye [NB*TE*HD];          // ent  pre-LN temp
__device__ __half g_QH[NB*NHD*TT*DHD];     // fp16 head-layout Q (pre-scaled 1/8)
__device__ __half g_KH[NB*NHD*TT*DHD];
__device__ __half g_VH[NB*NHD*TT*DHD];
// fp16 activations: rows 0..4607 word|CTX (per phase), 4096..4607 pos_ent, 4608..5119 ent
__device__ __half g_Xh[5120*1024];
__device__ __half g_Wt[8*1024*1024];       // 8 weights, transposed [N,K], fp16

// ---------------- helpers ----------------
__device__ __forceinline__ uint32_t smem_u32(const void* p){
    uint32_t a;
    asm("{ .reg .u64 t; cvta.to.shared.u64 t, %1; cvt.u32.u64 %0, t; }" : "=r"(a) : "l"(p));
    return a;
}
__device__ __forceinline__ uint32_t pkh(float a, float b){
    __half2 h = __floats2half2_rn(a, b);
    return *reinterpret_cast<uint32_t*>(&h);
}

#define CPA16(dst, src) asm volatile("cp.async.cg.shared.global [%0], [%1], 16;" :: "r"(dst), "l"(src))
#define CPA_COMMIT()    asm volatile("cp.async.commit_group;" ::: "memory")
template<int N> __device__ __forceinline__ void cpa_wait(){
    asm volatile("cp.async.wait_group %0;" :: "n"(N) : "memory");
}

__device__ __forceinline__ void ldsm4(uint32_t* r, uint32_t addr){
    asm volatile("ldmatrix.sync.aligned.m8n8.x4.shared.b16 {%0,%1,%2,%3}, [%4];"
        : "=r"(r[0]), "=r"(r[1]), "=r"(r[2]), "=r"(r[3]) : "r"(addr));
}
__device__ __forceinline__ void ldsm4t(uint32_t* r, uint32_t addr){
    asm volatile("ldmatrix.sync.aligned.m8n8.x4.trans.shared.b16 {%0,%1,%2,%3}, [%4];"
        : "=r"(r[0]), "=r"(r[1]), "=r"(r[2]), "=r"(r[3]) : "r"(addr));
}
__device__ __forceinline__ void mma16816h(float* d, const uint32_t* a, const uint32_t* b){
    asm volatile("mma.sync.aligned.m16n8k16.row.col.f32.f16.f16.f32 "
        "{%0,%1,%2,%3}, {%4,%5,%6,%7}, {%8,%9}, {%0,%1,%2,%3};"
        : "+f"(d[0]), "+f"(d[1]), "+f"(d[2]), "+f"(d[3])
        : "r"(a[0]), "r"(a[1]), "r"(a[2]), "r"(a[3]), "r"(b[0]), "r"(b[1]));
}

// ---------------- weight prep: transpose + fp16 ----------------
struct W8 { const float* p[8]; };

__global__ __launch_bounds__(256) void wprep_kernel(W8 ws, __half* outW){
    __shared__ float tile[32][33];
    const float* W = ws.p[blockIdx.z];
    int n0 = blockIdx.x * 32, k0 = blockIdx.y * 32;
    int tx = threadIdx.x & 31, ty = threadIdx.x >> 5;
    #pragma unroll
    for (int i = 0; i < 32; i += 8)
        tile[ty + i][tx] = W[(size_t)(k0 + ty + i) * 1024 + n0 + tx];
    __syncthreads();
    #pragma unroll
    for (int i = 0; i < 32; i += 8) {
        float f = tile[tx][ty + i];
        size_t o = ((size_t)blockIdx.z << 20) + ((size_t)(n0 + ty + i) << 10) + k0 + tx;
        outW[o] = __float2half_rn(f);
    }
}

// ---------------- activation prep (fp32 -> fp16) ----------------
__global__ void xprep_kernel(const float* __restrict__ X, __half* __restrict__ o){
    size_t i = (size_t)blockIdx.x * blockDim.x + threadIdx.x;
    float4 v = ((const float4*)X)[i];
    ((uint2*)o)[i] = make_uint2(pkh(v.x, v.y), pkh(v.z, v.w));
}
__global__ void pexprep_kernel(const float* __restrict__ ent, const float* __restrict__ qp,
                               __half* __restrict__ o){
    size_t i = (size_t)blockIdx.x * blockDim.x + threadIdx.x;
    float4 a = ((const float4*)ent)[i];
    float4 b = ((const float4*)qp)[i];
    ((uint2*)o)[i] = make_uint2(pkh((a.x+b.x)*0.5f, (a.y+b.y)*0.5f),
                                pkh((a.z+b.z)*0.5f, (a.w+b.w)*0.5f));
}

// ---------------- fp16 HMMA GEMM ----------------
#define STRB  144
#define OFF_B 18432
#define BUFSZ 36864
#define SMEM_GEMM (2*BUFSZ)

struct GemmCfg {
    const float* b0; const float* b1; const float* b2;
    void* o0; void* o1; void* o2;
    const float* res;
    int widx0, Tseg, Tfull, toff, mode, toffOut;
    int xbase01, xbase2;
};

__global__ __launch_bounds__(256, 2) void gemm_mma(
    const __half* __restrict__ Xh, const __half* __restrict__ WtAll, GemmCfg cfg)
{
    extern __shared__ char smc[];
    const uint32_t sb = smem_u32(smc);
    const int tid = threadIdx.x;
    const int wid = tid >> 5, lane = tid & 31;
    const int wm = wid >> 1, wn = wid & 1;
    const int z = blockIdx.z;

    const float* bias = (z == 0) ? cfg.b0 : (z == 1) ? cfg.b1 : cfg.b2;
    void* out         = (z == 0) ? cfg.o0 : (z == 1) ? cfg.o1 : cfg.o2;
    const __half* Wt = WtAll + ((size_t)(cfg.widx0 + z) << 20);
    const float oscale = (cfg.mode == 0 && z == 0) ? 0.125f : 1.f;

    const int m0 = blockIdx.y * 128;
    const int n0 = blockIdx.x * 128;
    const int b2 = m0 / cfg.Tseg;
    const int t0 = m0 - b2 * cfg.Tseg;
    const int xbase = (z == 2) ? cfg.xbase2 : cfg.xbase01;
    const __half* Ah = Xh + ((size_t)xbase + (size_t)b2 * cfg.Tfull + cfg.toff + t0) * HD;

    float acc[2][8][4];
    #pragma unroll
    for (int mt = 0; mt < 2; mt++)
        #pragma unroll
        for (int nt = 0; nt < 8; nt++)
            #pragma unroll
            for (int j = 0; j < 4; j++) acc[mt][nt][j] = 0.f;

    auto issue_chunk = [&](int ch, int buf){
        const int k0 = ch * 64;
        const uint32_t base = sb + buf * BUFSZ;
        #pragma unroll
        for (int i = 0; i < 4; i++) {
            int q = tid + i * 256;
            int r = q >> 3, s8 = q & 7;
            CPA16(base + r * STRB + s8 * 16,         Ah + (size_t)r * HD + k0 + s8 * 8);
            CPA16(base + OFF_B + r * STRB + s8 * 16, Wt + (size_t)(n0 + r) * HD + k0 + s8 * 8);
        }
    };

    issue_chunk(0, 0);
    CPA_COMMIT();

    const int arow = (lane & 7) + ((lane >> 3) & 1) * 8;
    const int acol8 = (lane >> 4) * 8;
    const int bnof = (lane & 7) + ((lane >> 4) << 3);
    const int bk8  = ((lane >> 3) & 1) * 8;

    int buf = 0;
    for (int ch = 0; ch < 16; ch++) {
        if (ch < 15) { issue_chunk(ch + 1, buf ^ 1); CPA_COMMIT(); cpa_wait<1>(); }
        else         { cpa_wait<0>(); }
        __syncthreads();

        const uint32_t base = sb + buf * BUFSZ;
        #pragma unroll
        for (int ks = 0; ks < 4; ks++) {
            uint32_t aF[2][4];
            #pragma unroll
            for (int mt = 0; mt < 2; mt++)
                ldsm4(aF[mt], base + (wm*32 + mt*16 + arow) * STRB + (ks*16 + acol8) * 2);
            uint32_t bF[4][4];
            #pragma unroll
            for (int np = 0; np < 4; np++)
                ldsm4(bF[np], base + OFF_B + (wn*64 + np*16 + bnof) * STRB + (ks*16 + bk8) * 2);
            #pragma unroll
            for (int mt = 0; mt < 2; mt++)
                #pragma unroll
                for (int nt = 0; nt < 8; nt++)
                    mma16816h(acc[mt][nt], aF[mt], &bF[nt >> 1][(nt & 1) * 2]);
        }
        __syncthreads();
        buf ^= 1;
    }

    // epilogue
    #pragma unroll
    for (int mt = 0; mt < 2; mt++) {
        #pragma unroll
        for (int hf = 0; hf < 2; hf++) {
            int lr = wm*32 + mt*16 + (lane >> 2) + hf*8;
            int t2 = t0 + lr;
            #pragma unroll
            for (int nt = 0; nt < 8; nt++) {
                int c = n0 + wn*64 + nt*8 + (lane & 3)*2;
                float v0 = acc[mt][nt][hf*2+0] + __ldg(bias + c);
                float v1 = acc[mt][nt][hf*2+1] + __ldg(bias + c + 1);
                if (cfg.mode == 0) {
                    int h = c >> 6, d = c & 63;
                    size_t o = (((size_t)(b2*NHD + h) * TT + cfg.toffOut + t2) << 6) + d;
                    *(uint32_t*)((__half*)out + o) = pkh(v0 * oscale, v1 * oscale);
                } else {
                    size_t o = (size_t)(m0 + lr) * HD + c;
                    float2 rr = *(const float2*)(cfg.res + o);
                    *(float2*)((float*)out + o) = make_float2(v0 + rr.x, v1 + rr.y);
                }
            }
        }
    }
}

// ---------------- fp16 flash attention (FA2 register path) ----------------
// grid (9, 64), 256 thr. SMEM halves stride 72 (144B). Q 18432 | K x2 | V x2 = 92160 B
#define AS_STR 72
#define AO_KF 18432
#define AO_VF 55296
#define ATTN_SMEM 92160

__global__ __launch_bounds__(256) void attn_tc(
    const __half* __restrict__ Q, const __half* __restrict__ K,
    const __half* __restrict__ V, const float* __restrict__ mask,
    __half* __restrict__ OutH)
{
    extern __shared__ char smc[];
    const uint32_t sbase = smem_u32(smc);

    const int tid = threadIdx.x, wid = tid >> 5, lane = tid & 31;
    const int bh = blockIdx.y, b = bh >> 4, h = bh & 15;
    const int q0 = blockIdx.x * 128;
    const __half* Qg = Q + ((size_t)bh * TT + q0) * DHD;
    const __half* Kg = K + (size_t)bh * TT * DHD;
    const __half* Vg = V + (size_t)bh * TT * DHD;
    const float* mb = mask + (size_t)b * TT;

    // tile loaders: 128 rows x 64 half = 8 segs/row
    auto loadQ = [&](){
        #pragma unroll
        for (int i = 0; i < 4; i++) {
            int q = tid + i * 256;
            int r = q >> 3, s = q & 7;
            CPA16(sbase + r * STRB + s * 16, Qg + (size_t)r * DHD + s * 8);
        }
    };
    auto issueKV = [&](int ch, int buf){
        const __half* ks = Kg + (size_t)ch * 128 * DHD;
        const __half* vs = Vg + (size_t)ch * 128 * DHD;
        uint32_t kd = sbase + AO_KF + buf * 18432;
        uint32_t vd = sbase + AO_VF + buf * 18432;
        #pragma unroll
        for (int i = 0; i < 4; i++) {
            int q = tid + i * 256;
            int r = q >> 3, s = q & 7;
            CPA16(kd + r * STRB + s * 16, ks + (size_t)r * DHD + s * 8);
            CPA16(vd + r * STRB + s * 16, vs + (size_t)r * DHD + s * 8);
        }
        CPA_COMMIT();
    };

    loadQ();
    issueKV(0, 0);   // group 0 includes Q + K0 + V0

    const int r4 = lane >> 2, c4 = lane & 3;
    const int row0 = wid * 16 + r4;
    const int arow16 = lane & 15, acol8 = (lane >> 4) * 8;
    const int bnof = (lane & 7) + ((lane >> 4) << 3);
    const int bk8  = ((lane >> 3) & 1) * 8;
    const int vgrp = lane >> 3, vwi = lane & 7;

    uint32_t aQ[4][4];
    float O[8][4];
    #pragma unroll
    for (int nt = 0; nt < 8; nt++)
        #pragma unroll
        for (int j = 0; j < 4; j++) O[nt][j] = 0.f;
    float m0 = -1e30f, m1 = -1e30f, l0 = 0.f, l1 = 0.f;

    int buf = 0;
    for (int ch = 0; ch < 9; ch++) {
        if (ch > 0) __syncthreads();              // buf^1 fully consumed
        if (ch < 8) { issueKV(ch + 1, buf ^ 1); cpa_wait<1>(); }
        else        { cpa_wait<0>(); }
        __syncthreads();

        if (ch == 0) {
            #pragma unroll
            for (int ks = 0; ks < 4; ks++)
                ldsm4(aQ[ks], sbase + (wid*16 + arow16) * STRB + (ks*16 + acol8) * 2);
        }

        const uint32_t kb = sbase + AO_KF + buf * 18432;
        const uint32_t vb = sbase + AO_VF + buf * 18432;

        // ---- S = Qs @ K^T (Q pre-scaled by 1/8) ----
        float S[16][4];
        #pragma unroll
        for (int nt = 0; nt < 16; nt++)
            #pragma unroll
            for (int j = 0; j < 4; j++) S[nt][j] = 0.f;

        #pragma unroll
        for (int ntp = 0; ntp < 8; ntp++) {
            #pragma unroll
            for (int ks = 0; ks < 4; ks++) {
                uint32_t bF[4];
                ldsm4(bF, kb + (ntp*16 + bnof) * STRB + (ks*16 + bk8) * 2);
                mma16816h(S[2*ntp],     aQ[ks], &bF[0]);
                mma16816h(S[2*ntp + 1], aQ[ks], &bF[2]);
            }
        }

        // ---- mask + online softmax ----
        const int kgl = ch * 128;
        float mt0 = -1e30f, mt1 = -1e30f;
        #pragma unroll
        for (int nt = 0; nt < 16; nt++) {
            float2 mk = __ldg((const float2*)(mb + kgl + nt*8 + 2*c4));
            S[nt][0] += mk.x;
            S[nt][1] += mk.y;
            S[nt][2] += mk.x;
            S[nt][3] += mk.y;
            mt0 = fmaxf(mt0, fmaxf(S[nt][0], S[nt][1]));
            mt1 = fmaxf(mt1, fmaxf(S[nt][2], S[nt][3]));
        }
        mt0 = fmaxf(mt0, __shfl_xor_sync(0xffffffffu, mt0, 1));
        mt0 = fmaxf(mt0, __shfl_xor_sync(0xffffffffu, mt0, 2));
        mt1 = fmaxf(mt1, __shfl_xor_sync(0xffffffffu, mt1, 1));
        mt1 = fmaxf(mt1, __shfl_xor_sync(0xffffffffu, mt1, 2));

        float mn0 = fmaxf(m0, mt0), mn1 = fmaxf(m1, mt1);
        float al0 = __expf(m0 - mn0), al1 = __expf(m1 - mn1);
        #pragma unroll
        for (int nt = 0; nt < 8; nt++) {
            O[nt][0] *= al0; O[nt][1] *= al0;
            O[nt][2] *= al1; O[nt][3] *= al1;
        }

        float ls0 = 0.f, ls1 = 0.f;
        #pragma unroll
        for (int nt = 0; nt < 16; nt++) {
            S[nt][0] = __expf(S[nt][0] - mn0);
            S[nt][1] = __expf(S[nt][1] - mn0);
            S[nt][2] = __expf(S[nt][2] - mn1);
            S[nt][3] = __expf(S[nt][3] - mn1);
            ls0 += S[nt][0] + S[nt][1];
            ls1 += S[nt][2] + S[nt][3];
        }
        ls0 += __shfl_xor_sync(0xffffffffu, ls0, 1);
        ls0 += __shfl_xor_sync(0xffffffffu, ls0, 2);
        ls1 += __shfl_xor_sync(0xffffffffu, ls1, 1);
        ls1 += __shfl_xor_sync(0xffffffffu, ls1, 2);
        l0 = l0 * al0 + ls0; m0 = mn0;
        l1 = l1 * al1 + ls1; m1 = mn1;

        // ---- O += P @ V : P fed from registers as A fragments ----
        #pragma unroll
        for (int t = 0; t < 8; t++) {
            uint32_t aP[4];
            aP[0] = pkh(S[2*t][0],     S[2*t][1]);
            aP[1] = pkh(S[2*t][2],     S[2*t][3]);
            aP[2] = pkh(S[2*t + 1][0], S[2*t + 1][1]);
            aP[3] = pkh(S[2*t + 1][2], S[2*t + 1][3]);
            #pragma unroll
            for (int dp = 0; dp < 4; dp++) {
                uint32_t bF[4];
                ldsm4t(bF, vb + (t*16 + (vgrp & 1)*8 + vwi) * STRB + (dp*16 + (vgrp >> 1)*8) * 2);
                mma16816h(O[2*dp],     aP, &bF[0]);
                mma16816h(O[2*dp + 1], aP, &bF[2]);
            }
        }
        buf ^= 1;
    }

    float i0 = 1.f / l0, i1 = 1.f / l1;
    #pragma unroll
    for (int nt = 0; nt < 8; nt++) {
        int c = h * 64 + nt*8 + 2*c4;
        size_t o0 = (size_t)(b * TT + q0 + row0) * HD + c;
        size_t o1 = (size_t)(b * TT + q0 + row0 + 8) * HD + c;
        *(uint32_t*)(OutH + o0) = pkh(O[nt][0] * i0, O[nt][1] * i0);
        *(uint32_t*)(OutH + o1) = pkh(O[nt][2] * i1, O[nt][3] * i1);
    }
}

// ---------------- layernorm ----------------
__device__ __forceinline__ float block_sum(float v, float* sh) {
    #pragma unroll
    for (int o = 16; o; o >>= 1) v += __shfl_xor_sync(0xffffffffu, v, o);
    int tid = threadIdx.x;
    if ((tid & 31) == 0) sh[tid >> 5] = v;
    __syncthreads();
    if (tid < 32) {
        float t = (tid < 8) ? sh[tid] : 0.f;
        #pragma unroll
        for (int o = 4; o; o >>= 1) t += __shfl_xor_sync(0xffffffffu, t, o);
        if (tid == 0) sh[0] = t;
    }
    __syncthreads();
    float r = sh[0];
    __syncthreads();
    return r;
}

__global__ __launch_bounds__(256) void ln_kernel(
    const float* __restrict__ Y, const float* __restrict__ g,
    const float* __restrict__ bt, float* __restrict__ out)
{
    __shared__ float sh[8];
    int row = blockIdx.x, tid = threadIdx.x;
    float4 v = ((const float4*)(Y + (size_t)row * HD))[tid];
    float mu = block_sum(v.x + v.y + v.z + v.w, sh) * (1.f / HD);
    float4 d = make_float4(v.x - mu, v.y - mu, v.z - mu, v.w - mu);
    float var = block_sum(d.x*d.x + d.y*d.y + d.z*d.z + d.w*d.w, sh) * (1.f / HD);
    float rs = rsqrtf(var + 1e-12f);
    float4 gg = ((const float4*)g)[tid];
    float4 bb = ((const float4*)bt)[tid];
    ((float4*)(out + (size_t)row * HD))[tid] =
        make_float4(d.x*rs*gg.x + bb.x, d.y*rs*gg.y + bb.y, d.z*rs*gg.z + bb.z, d.w*rs*gg.w + bb.w);
}

// ---------------- launch ----------------
extern "C" void kernel_launch(void* const* d_in, const int* in_sizes, int n_in,
                              void* d_out, int out_size)
{
    (void)in_sizes; (void)n_in; (void)out_size;
    const float* word = (const float*)d_in[0];
    const float* ent  = (const float*)d_in[1];
    const float* mask = (const float*)d_in[2];
    const float* qpos = (const float*)d_in[3];
    const float* Wq  = (const float*)d_in[4];   const float* bq  = (const float*)d_in[5];
    const float* Wk  = (const float*)d_in[6];   const float* bk  = (const float*)d_in[7];
    const float* Wv  = (const float*)d_in[8];   const float* bv  = (const float*)d_in[9];
    const float* Weq = (const float*)d_in[10];  const float* beq = (const float*)d_in[11];
    const float* Wek = (const float*)d_in[12];  const float* bek = (const float*)d_in[13];
    const float* Wev = (const float*)d_in[14];  const float* bev = (const float*)d_in[15];
    const float* Wo  = (const float*)d_in[16];  const float* bo  = (const float*)d_in[17];
    const float* Weo = (const float*)d_in[18];  const float* beo = (const float*)d_in[19];
    const float* lng  = (const float*)d_in[20]; const float* lnb  = (const float*)d_in[21];
    const float* elng = (const float*)d_in[22]; const float* elnb = (const float*)d_in[23];
    float* out = (float*)d_out;

    float *Yw, *Ye;
    __half *QH, *KH, *VH, *Xh, *Wt;
    cudaGetSymbolAddress((void**)&Yw, g_Yw);
    cudaGetSymbolAddress((void**)&Ye, g_Ye);
    cudaGetSymbolAddress((void**)&QH, g_QH);
    cudaGetSymbolAddress((void**)&KH, g_KH);
    cudaGetSymbolAddress((void**)&VH, g_VH);
    cudaGetSymbolAddress((void**)&Xh, g_Xh);
    cudaGetSymbolAddress((void**)&Wt, g_Wt);

    cudaFuncSetAttribute(gemm_mma, cudaFuncAttributeMaxDynamicSharedMemorySize, SMEM_GEMM);
    cudaFuncSetAttribute(attn_tc, cudaFuncAttributeMaxDynamicSharedMemorySize, ATTN_SMEM);

    // 0. weight prep
    W8 w8; w8.p[0]=Wq; w8.p[1]=Wk; w8.p[2]=Wv; w8.p[3]=Weq; w8.p[4]=Wek; w8.p[5]=Wev; w8.p[6]=Wo; w8.p[7]=Weo;
    wprep_kernel<<<dim3(32, 32, 8), 256>>>(w8, Wt);

    // 1. activation prep
    xprep_kernel <<<(NB*TW*HD/4)/256, 256>>>(word, Xh);
    pexprep_kernel<<<(NB*TE*HD/4)/256, 256>>>(ent, qpos, Xh + (size_t)4096*HD);
    xprep_kernel <<<(NB*TE*HD/4)/256, 256>>>(ent, Xh + (size_t)4608*HD);

    // 2. projections -> fp16 head layout (Q pre-scaled by 1/8)
    GemmCfg c1 = {};
    c1.b0 = bq; c1.b1 = bk; c1.b2 = bv;
    c1.o0 = QH; c1.o1 = KH; c1.o2 = VH;
    c1.widx0 = 0; c1.Tseg = TW; c1.Tfull = TW; c1.toff = 0; c1.mode = 0; c1.toffOut = 0;
    c1.xbase01 = 0; c1.xbase2 = 0;
    gemm_mma<<<dim3(8, (NB*TW)/128, 3), 256, SMEM_GEMM>>>(Xh, Wt, c1);

    GemmCfg c2 = {};
    c2.b0 = beq; c2.b1 = bek; c2.b2 = bev;
    c2.o0 = QH; c2.o1 = KH; c2.o2 = VH;
    c2.widx0 = 3; c2.Tseg = TE; c2.Tfull = TE; c2.toff = 0; c2.mode = 0; c2.toffOut = TW;
    c2.xbase01 = 4096; c2.xbase2 = 4608;
    gemm_mma<<<dim3(8, (NB*TE)/128, 3), 256, SMEM_GEMM>>>(Xh, Wt, c2);

    // 3. attention (fp16) -> writes CTX as fp16 directly into Xh rows [0, 4608)
    attn_tc<<<dim3(TT/128, NB*NHD), 256, ATTN_SMEM>>>(QH, KH, VH, mask, Xh);

    // 4. output projections + residual (fp32 out into Y temps)
    GemmCfg c3 = {};
    c3.b0 = bo; c3.o0 = Yw; c3.res = word;
    c3.widx0 = 6; c3.Tseg = TW; c3.Tfull = TT; c3.toff = 0; c3.mode = 1;
    c3.xbase01 = 0; c3.xbase2 = 0;
    gemm_mma<<<dim3(8, (NB*TW)/128, 1), 256, SMEM_GEMM>>>(Xh, Wt, c3);

    GemmCfg c4 = {};
    c4.b0 = beo; c4.o0 = Ye; c4.res = ent;
    c4.widx0 = 7; c4.Tseg = TE; c4.Tfull = TT; c4.toff = TW; c4.mode = 1;
    c4.xbase01 = 0; c4.xbase2 = 0;
    gemm_mma<<<dim3(8, (NB*TE)/128, 1), 256, SMEM_GEMM>>>(Xh, Wt, c4);

    // 5. layernorm
    ln_kernel<<<NB * TW, 256>>>(Yw, lng, lnb, out);
    ln_kernel<<<NB * TE, 256>>>(Ye, elng, elnb, out + (size_t)NB * TW * HD);
}

// round 7
// speedup vs baseline: 10.3090x; 1.1773x over previous
#include <cuda_runtime.h>
#include <cuda_bf16.h>
#include <cuda_fp16.h>
#include <stdint.h>
#include <math.h>

#define NB  4
#define TW  1024
#define TE  128
#define TT  1152
#define HD  1024
#define NHD 16
#define DHD 64

// ---------------- scratch ----------------
__device__ float g_Y  [(NB*TW + NB*TE)*HD];   // unified pre-LN temp (word rows 0..4095, ent 4096..4607)
__device__ __half g_QH[NB*NHD*TT*DHD];        // fp16 head-layout Q (pre-scaled 1/8)
__device__ __half g_KH[NB*NHD*TT*DHD];
__device__ __half g_VH[NB*NHD*TT*DHD];
// fp16 activations: rows 0..4095 word (later CTX 0..4607), 4096..4607 pos_ent, 4608..5119 ent
__device__ __half g_Xh[5120*1024];
__device__ __half g_Wt[8*1024*1024];          // 8 weights, transposed [N,K], fp16

// ---------------- helpers ----------------
__device__ __forceinline__ uint32_t smem_u32(const void* p){
    uint32_t a;
    asm("{ .reg .u64 t; cvta.to.shared.u64 t, %1; cvt.u32.u64 %0, t; }" : "=r"(a) : "l"(p));
    return a;
}
__device__ __forceinline__ uint32_t pkh(float a, float b){
    __half2 h = __floats2half2_rn(a, b);
    return *reinterpret_cast<uint32_t*>(&h);
}

#define CPA16(dst, src) asm volatile("cp.async.cg.shared.global [%0], [%1], 16;" :: "r"(dst), "l"(src))
#define CPA_COMMIT()    asm volatile("cp.async.commit_group;" ::: "memory")
template<int N> __device__ __forceinline__ void cpa_wait(){
    asm volatile("cp.async.wait_group %0;" :: "n"(N) : "memory");
}

__device__ __forceinline__ void ldsm4(uint32_t* r, uint32_t addr){
    asm volatile("ldmatrix.sync.aligned.m8n8.x4.shared.b16 {%0,%1,%2,%3}, [%4];"
        : "=r"(r[0]), "=r"(r[1]), "=r"(r[2]), "=r"(r[3]) : "r"(addr));
}
__device__ __forceinline__ void ldsm4t(uint32_t* r, uint32_t addr){
    asm volatile("ldmatrix.sync.aligned.m8n8.x4.trans.shared.b16 {%0,%1,%2,%3}, [%4];"
        : "=r"(r[0]), "=r"(r[1]), "=r"(r[2]), "=r"(r[3]) : "r"(addr));
}
__device__ __forceinline__ void mma16816h(float* d, const uint32_t* a, const uint32_t* b){
    asm volatile("mma.sync.aligned.m16n8k16.row.col.f32.f16.f16.f32 "
        "{%0,%1,%2,%3}, {%4,%5,%6,%7}, {%8,%9}, {%0,%1,%2,%3};"
        : "+f"(d[0]), "+f"(d[1]), "+f"(d[2]), "+f"(d[3])
        : "r"(a[0]), "r"(a[1]), "r"(a[2]), "r"(a[3]), "r"(b[0]), "r"(b[1]));
}

// ---------------- unified prep: weights (z<8) + activations (z==8) ----------------
struct PrepArgs {
    const float* w[8];
    const float* word; const float* ent; const float* qp;
};

__global__ __launch_bounds__(256) void prep_kernel(PrepArgs pa, __half* Wt, __half* Xh){
    __shared__ float tile[32][33];
    const int z = blockIdx.z;
    if (z < 8) {
        if (blockIdx.x >= 1024) return;
        const float* W = pa.w[z];
        int n0 = (blockIdx.x & 31) * 32, k0 = (blockIdx.x >> 5) * 32;
        int tx = threadIdx.x & 31, ty = threadIdx.x >> 5;
        #pragma unroll
        for (int i = 0; i < 32; i += 8)
            tile[ty + i][tx] = W[(size_t)(k0 + ty + i) * 1024 + n0 + tx];
        __syncthreads();
        #pragma unroll
        for (int i = 0; i < 32; i += 8) {
            float f = tile[tx][ty + i];
            size_t o = ((size_t)z << 20) + ((size_t)(n0 + ty + i) << 10) + k0 + tx;
            Wt[o] = __float2half_rn(f);
        }
    } else {
        // activations: 1280 blocks x 1024 float4 (4 rows per block, region-aligned)
        size_t base4 = (size_t)blockIdx.x * 1024;
        #pragma unroll
        for (int i = 0; i < 4; i++) {
            size_t idx4 = base4 + threadIdx.x + i * 256;
            size_t row = idx4 >> 8;                     // 256 float4 per row
            float4 v;
            if (row < 4096) {
                v = ((const float4*)pa.word)[idx4];
            } else if (row < 4608) {
                size_t off = idx4 - (size_t)4096 * 256;
                float4 a = ((const float4*)pa.ent)[off];
                float4 b = ((const float4*)pa.qp)[off];
                v = make_float4((a.x+b.x)*0.5f,(a.y+b.y)*0.5f,(a.z+b.z)*0.5f,(a.w+b.w)*0.5f);
            } else {
                size_t off = idx4 - (size_t)4608 * 256;
                v = ((const float4*)pa.ent)[off];
            }
            ((uint2*)Xh)[idx4] = make_uint2(pkh(v.x, v.y), pkh(v.z, v.w));
        }
    }
}

// ---------------- fp16 HMMA GEMM (two segments per launch) ----------------
#define STRB  144
#define OFF_B 18432
#define BUFSZ 36864
#define SMEM_GEMM (2*BUFSZ)

struct GemmCfg {
    const float* bias0[3]; const float* bias1[3];
    void* o[3];
    const float* res0; const float* res1;
    int widx0, widx1;
    int mode;            // 0: scatter fp16 head layout, 1: fp32 + residual into Y
    int ySplit;          // y >= ySplit -> segment 1
    int Tseg0, Tfull0, toff0, toffOut0, xb01_0, xb2_0;
    int Tseg1, Tfull1, toff1, toffOut1, xb01_1, xb2_1;
    int outRowBase1;     // mode 1: global Y row base for segment 1
};

__global__ __launch_bounds__(256, 2) void gemm_mma(
    const __half* __restrict__ Xh, const __half* __restrict__ WtAll, GemmCfg cfg)
{
    extern __shared__ char smc[];
    const uint32_t sb = smem_u32(smc);
    const int tid = threadIdx.x;
    const int wid = tid >> 5, lane = tid & 31;
    const int wm = wid >> 1, wn = wid & 1;
    const int z = blockIdx.z;

    const int seg = (blockIdx.y >= cfg.ySplit) ? 1 : 0;
    const int yy  = seg ? blockIdx.y - cfg.ySplit : blockIdx.y;

    const float* bias = (seg ? cfg.bias1 : cfg.bias0)[z];
    void* out = cfg.o[z];
    const int Tseg    = seg ? cfg.Tseg1    : cfg.Tseg0;
    const int Tfull   = seg ? cfg.Tfull1   : cfg.Tfull0;
    const int toff    = seg ? cfg.toff1    : cfg.toff0;
    const int toffOut = seg ? cfg.toffOut1 : cfg.toffOut0;
    const int xb      = (z == 2) ? (seg ? cfg.xb2_1 : cfg.xb2_0)
                                 : (seg ? cfg.xb01_1 : cfg.xb01_0);
    const float* res  = seg ? cfg.res1 : cfg.res0;
    const int widx    = (seg ? cfg.widx1 : cfg.widx0) + z;
    const int outBase = seg ? cfg.outRowBase1 : 0;

    const __half* Wt = WtAll + ((size_t)widx << 20);
    const float oscale = (cfg.mode == 0 && z == 0) ? 0.125f : 1.f;

    const int m0 = yy * 128;                 // local row within segment
    const int n0 = blockIdx.x * 128;
    const int b2 = m0 / Tseg;
    const int t0 = m0 - b2 * Tseg;
    const __half* Ah = Xh + ((size_t)xb + (size_t)b2 * Tfull + toff + t0) * HD;

    float acc[2][8][4];
    #pragma unroll
    for (int mt = 0; mt < 2; mt++)
        #pragma unroll
        for (int nt = 0; nt < 8; nt++)
            #pragma unroll
            for (int j = 0; j < 4; j++) acc[mt][nt][j] = 0.f;

    auto issue_chunk = [&](int ch, int buf){
        const int k0 = ch * 64;
        const uint32_t base = sb + buf * BUFSZ;
        #pragma unroll
        for (int i = 0; i < 4; i++) {
            int q = tid + i * 256;
            int r = q >> 3, s8 = q & 7;
            CPA16(base + r * STRB + s8 * 16,         Ah + (size_t)r * HD + k0 + s8 * 8);
            CPA16(base + OFF_B + r * STRB + s8 * 16, Wt + (size_t)(n0 + r) * HD + k0 + s8 * 8);
        }
    };

    issue_chunk(0, 0);
    CPA_COMMIT();

    const int arow = (lane & 7) + ((lane >> 3) & 1) * 8;
    const int acol8 = (lane >> 4) * 8;
    const int bnof = (lane & 7) + ((lane >> 4) << 3);
    const int bk8  = ((lane >> 3) & 1) * 8;

    int buf = 0;
    for (int ch = 0; ch < 16; ch++) {
        if (ch < 15) { issue_chunk(ch + 1, buf ^ 1); CPA_COMMIT(); cpa_wait<1>(); }
        else         { cpa_wait<0>(); }
        __syncthreads();

        const uint32_t base = sb + buf * BUFSZ;
        #pragma unroll
        for (int ks = 0; ks < 4; ks++) {
            uint32_t aF[2][4];
            #pragma unroll
            for (int mt = 0; mt < 2; mt++)
                ldsm4(aF[mt], base + (wm*32 + mt*16 + arow) * STRB + (ks*16 + acol8) * 2);
            uint32_t bF[4][4];
            #pragma unroll
            for (int np = 0; np < 4; np++)
                ldsm4(bF[np], base + OFF_B + (wn*64 + np*16 + bnof) * STRB + (ks*16 + bk8) * 2);
            #pragma unroll
            for (int mt = 0; mt < 2; mt++)
                #pragma unroll
                for (int nt = 0; nt < 8; nt++)
                    mma16816h(acc[mt][nt], aF[mt], &bF[nt >> 1][(nt & 1) * 2]);
        }
        __syncthreads();
        buf ^= 1;
    }

    // epilogue
    #pragma unroll
    for (int mt = 0; mt < 2; mt++) {
        #pragma unroll
        for (int hf = 0; hf < 2; hf++) {
            int lr = wm*32 + mt*16 + (lane >> 2) + hf*8;
            int t2 = t0 + lr;
            #pragma unroll
            for (int nt = 0; nt < 8; nt++) {
                int c = n0 + wn*64 + nt*8 + (lane & 3)*2;
                float v0 = acc[mt][nt][hf*2+0] + __ldg(bias + c);
                float v1 = acc[mt][nt][hf*2+1] + __ldg(bias + c + 1);
                if (cfg.mode == 0) {
                    int h = c >> 6, d = c & 63;
                    size_t o = (((size_t)(b2*NHD + h) * TT + toffOut + t2) << 6) + d;
                    *(uint32_t*)((__half*)out + o) = pkh(v0 * oscale, v1 * oscale);
                } else {
                    size_t ro = (size_t)(m0 + lr) * HD + c;           // residual (segment-local)
                    float2 rr = *(const float2*)(res + ro);
                    size_t oo = (size_t)(outBase + m0 + lr) * HD + c; // unified Y
                    *(float2*)((float*)out + oo) = make_float2(v0 + rr.x, v1 + rr.y);
                }
            }
        }
    }
}

// ---------------- fp16 flash attention (FA2 register path) ----------------
#define AO_KF 18432
#define AO_VF 55296
#define ATTN_SMEM 92160

__global__ __launch_bounds__(256) void attn_tc(
    const __half* __restrict__ Q, const __half* __restrict__ K,
    const __half* __restrict__ V, const float* __restrict__ mask,
    __half* __restrict__ OutH)
{
    extern __shared__ char smc[];
    const uint32_t sbase = smem_u32(smc);

    const int tid = threadIdx.x, wid = tid >> 5, lane = tid & 31;
    const int bh = blockIdx.y, b = bh >> 4, h = bh & 15;
    const int q0 = blockIdx.x * 128;
    const __half* Qg = Q + ((size_t)bh * TT + q0) * DHD;
    const __half* Kg = K + (size_t)bh * TT * DHD;
    const __half* Vg = V + (size_t)bh * TT * DHD;
    const float* mb = mask + (size_t)b * TT;

    auto loadQ = [&](){
        #pragma unroll
        for (int i = 0; i < 4; i++) {
            int q = tid + i * 256;
            int r = q >> 3, s = q & 7;
            CPA16(sbase + r * STRB + s * 16, Qg + (size_t)r * DHD + s * 8);
        }
    };
    auto issueKV = [&](int ch, int buf){
        const __half* ks = Kg + (size_t)ch * 128 * DHD;
        const __half* vs = Vg + (size_t)ch * 128 * DHD;
        uint32_t kd = sbase + AO_KF + buf * 18432;
        uint32_t vd = sbase + AO_VF + buf * 18432;
        #pragma unroll
        for (int i = 0; i < 4; i++) {
            int q = tid + i * 256;
            int r = q >> 3, s = q & 7;
            CPA16(kd + r * STRB + s * 16, ks + (size_t)r * DHD + s * 8);
            CPA16(vd + r * STRB + s * 16, vs + (size_t)r * DHD + s * 8);
        }
        CPA_COMMIT();
    };

    loadQ();
    issueKV(0, 0);

    const int r4 = lane >> 2, c4 = lane & 3;
    const int row0 = wid * 16 + r4;
    const int arow16 = lane & 15, acol8 = (lane >> 4) * 8;
    const int bnof = (lane & 7) + ((lane >> 4) << 3);
    const int bk8  = ((lane >> 3) & 1) * 8;
    const int vgrp = lane >> 3, vwi = lane & 7;

    uint32_t aQ[4][4];
    float O[8][4];
    #pragma unroll
    for (int nt = 0; nt < 8; nt++)
        #pragma unroll
        for (int j = 0; j < 4; j++) O[nt][j] = 0.f;
    float m0 = -1e30f, m1 = -1e30f, l0 = 0.f, l1 = 0.f;

    int buf = 0;
    for (int ch = 0; ch < 9; ch++) {
        if (ch > 0) __syncthreads();
        if (ch < 8) { issueKV(ch + 1, buf ^ 1); cpa_wait<1>(); }
        else        { cpa_wait<0>(); }
        __syncthreads();

        if (ch == 0) {
            #pragma unroll
            for (int ks = 0; ks < 4; ks++)
                ldsm4(aQ[ks], sbase + (wid*16 + arow16) * STRB + (ks*16 + acol8) * 2);
        }

        const uint32_t kb = sbase + AO_KF + buf * 18432;
        const uint32_t vb = sbase + AO_VF + buf * 18432;

        float S[16][4];
        #pragma unroll
        for (int nt = 0; nt < 16; nt++)
            #pragma unroll
            for (int j = 0; j < 4; j++) S[nt][j] = 0.f;

        #pragma unroll
        for (int ntp = 0; ntp < 8; ntp++) {
            #pragma unroll
            for (int ks = 0; ks < 4; ks++) {
                uint32_t bF[4];
                ldsm4(bF, kb + (ntp*16 + bnof) * STRB + (ks*16 + bk8) * 2);
                mma16816h(S[2*ntp],     aQ[ks], &bF[0]);
                mma16816h(S[2*ntp + 1], aQ[ks], &bF[2]);
            }
        }

        const int kgl = ch * 128;
        float mt0 = -1e30f, mt1 = -1e30f;
        #pragma unroll
        for (int nt = 0; nt < 16; nt++) {
            float2 mk = __ldg((const float2*)(mb + kgl + nt*8 + 2*c4));
            S[nt][0] += mk.x;
            S[nt][1] += mk.y;
            S[nt][2] += mk.x;
            S[nt][3] += mk.y;
            mt0 = fmaxf(mt0, fmaxf(S[nt][0], S[nt][1]));
            mt1 = fmaxf(mt1, fmaxf(S[nt][2], S[nt][3]));
        }
        mt0 = fmaxf(mt0, __shfl_xor_sync(0xffffffffu, mt0, 1));
        mt0 = fmaxf(mt0, __shfl_xor_sync(0xffffffffu, mt0, 2));
        mt1 = fmaxf(mt1, __shfl_xor_sync(0xffffffffu, mt1, 1));
        mt1 = fmaxf(mt1, __shfl_xor_sync(0xffffffffu, mt1, 2));

        float mn0 = fmaxf(m0, mt0), mn1 = fmaxf(m1, mt1);
        float al0 = __expf(m0 - mn0), al1 = __expf(m1 - mn1);
        #pragma unroll
        for (int nt = 0; nt < 8; nt++) {
            O[nt][0] *= al0; O[nt][1] *= al0;
            O[nt][2] *= al1; O[nt][3] *= al1;
        }

        float ls0 = 0.f, ls1 = 0.f;
        #pragma unroll
        for (int nt = 0; nt < 16; nt++) {
            S[nt][0] = __expf(S[nt][0] - mn0);
            S[nt][1] = __expf(S[nt][1] - mn0);
            S[nt][2] = __expf(S[nt][2] - mn1);
            S[nt][3] = __expf(S[nt][3] - mn1);
            ls0 += S[nt][0] + S[nt][1];
            ls1 += S[nt][2] + S[nt][3];
        }
        ls0 += __shfl_xor_sync(0xffffffffu, ls0, 1);
        ls0 += __shfl_xor_sync(0xffffffffu, ls0, 2);
        ls1 += __shfl_xor_sync(0xffffffffu, ls1, 1);
        ls1 += __shfl_xor_sync(0xffffffffu, ls1, 2);
        l0 = l0 * al0 + ls0; m0 = mn0;
        l1 = l1 * al1 + ls1; m1 = mn1;

        #pragma unroll
        for (int t = 0; t < 8; t++) {
            uint32_t aP[4];
            aP[0] = pkh(S[2*t][0],     S[2*t][1]);
            aP[1] = pkh(S[2*t][2],     S[2*t][3]);
            aP[2] = pkh(S[2*t + 1][0], S[2*t + 1][1]);
            aP[3] = pkh(S[2*t + 1][2], S[2*t + 1][3]);
            #pragma unroll
            for (int dp = 0; dp < 4; dp++) {
                uint32_t bF[4];
                ldsm4t(bF, vb + (t*16 + (vgrp & 1)*8 + vwi) * STRB + (dp*16 + (vgrp >> 1)*8) * 2);
                mma16816h(O[2*dp],     aP, &bF[0]);
                mma16816h(O[2*dp + 1], aP, &bF[2]);
            }
        }
        buf ^= 1;
    }

    float i0 = 1.f / l0, i1 = 1.f / l1;
    #pragma unroll
    for (int nt = 0; nt < 8; nt++) {
        int c = h * 64 + nt*8 + 2*c4;
        size_t o0 = (size_t)(b * TT + q0 + row0) * HD + c;
        size_t o1 = (size_t)(b * TT + q0 + row0 + 8) * HD + c;
        *(uint32_t*)(OutH + o0) = pkh(O[nt][0] * i0, O[nt][1] * i0);
        *(uint32_t*)(OutH + o1) = pkh(O[nt][2] * i1, O[nt][3] * i1);
    }
}

// ---------------- layernorm (unified word+ent) ----------------
__device__ __forceinline__ float block_sum(float v, float* sh) {
    #pragma unroll
    for (int o = 16; o; o >>= 1) v += __shfl_xor_sync(0xffffffffu, v, o);
    int tid = threadIdx.x;
    if ((tid & 31) == 0) sh[tid >> 5] = v;
    __syncthreads();
    if (tid < 32) {
        float t = (tid < 8) ? sh[tid] : 0.f;
        #pragma unroll
        for (int o = 4; o; o >>= 1) t += __shfl_xor_sync(0xffffffffu, t, o);
        if (tid == 0) sh[0] = t;
    }
    __syncthreads();
    float r = sh[0];
    __syncthreads();
    return r;
}

__global__ __launch_bounds__(256) void ln_kernel(
    const float* __restrict__ Y,
    const float* __restrict__ g0, const float* __restrict__ b0,
    const float* __restrict__ g1, const float* __restrict__ b1,
    float* __restrict__ out)
{
    __shared__ float sh[8];
    int row = blockIdx.x, tid = threadIdx.x;
    const float* g  = (row < NB*TW) ? g0 : g1;
    const float* bt = (row < NB*TW) ? b0 : b1;
    float4 v = ((const float4*)(Y + (size_t)row * HD))[tid];
    float mu = block_sum(v.x + v.y + v.z + v.w, sh) * (1.f / HD);
    float4 d = make_float4(v.x - mu, v.y - mu, v.z - mu, v.w - mu);
    float var = block_sum(d.x*d.x + d.y*d.y + d.z*d.z + d.w*d.w, sh) * (1.f / HD);
    float rs = rsqrtf(var + 1e-12f);
    float4 gg = ((const float4*)g)[tid];
    float4 bb = ((const float4*)bt)[tid];
    ((float4*)(out + (size_t)row * HD))[tid] =
        make_float4(d.x*rs*gg.x + bb.x, d.y*rs*gg.y + bb.y, d.z*rs*gg.z + bb.z, d.w*rs*gg.w + bb.w);
}

// ---------------- launch ----------------
extern "C" void kernel_launch(void* const* d_in, const int* in_sizes, int n_in,
                              void* d_out, int out_size)
{
    (void)in_sizes; (void)n_in; (void)out_size;
    const float* word = (const float*)d_in[0];
    const float* ent  = (const float*)d_in[1];
    const float* mask = (const float*)d_in[2];
    const float* qpos = (const float*)d_in[3];
    const float* Wq  = (const float*)d_in[4];   const float* bq  = (const float*)d_in[5];
    const float* Wk  = (const float*)d_in[6];   const float* bk  = (const float*)d_in[7];
    const float* Wv  = (const float*)d_in[8];   const float* bv  = (const float*)d_in[9];
    const float* Weq = (const float*)d_in[10];  const float* beq = (const float*)d_in[11];
    const float* Wek = (const float*)d_in[12];  const float* bek = (const float*)d_in[13];
    const float* Wev = (const float*)d_in[14];  const float* bev = (const float*)d_in[15];
    const float* Wo  = (const float*)d_in[16];  const float* bo  = (const float*)d_in[17];
    const float* Weo = (const float*)d_in[18];  const float* beo = (const float*)d_in[19];
    const float* lng  = (const float*)d_in[20]; const float* lnb  = (const float*)d_in[21];
    const float* elng = (const float*)d_in[22]; const float* elnb = (const float*)d_in[23];
    float* out = (float*)d_out;

    float *Y;
    __half *QH, *KH, *VH, *Xh, *Wt;
    cudaGetSymbolAddress((void**)&Y,  g_Y);
    cudaGetSymbolAddress((void**)&QH, g_QH);
    cudaGetSymbolAddress((void**)&KH, g_KH);
    cudaGetSymbolAddress((void**)&VH, g_VH);
    cudaGetSymbolAddress((void**)&Xh, g_Xh);
    cudaGetSymbolAddress((void**)&Wt, g_Wt);

    cudaFuncSetAttribute(gemm_mma, cudaFuncAttributeMaxDynamicSharedMemorySize, SMEM_GEMM);
    cudaFuncSetAttribute(attn_tc, cudaFuncAttributeMaxDynamicSharedMemorySize, ATTN_SMEM);

    // 1. unified prep (weights + activations)
    PrepArgs pa;
    pa.w[0]=Wq; pa.w[1]=Wk; pa.w[2]=Wv; pa.w[3]=Weq; pa.w[4]=Wek; pa.w[5]=Wev; pa.w[6]=Wo; pa.w[7]=Weo;
    pa.word = word; pa.ent = ent; pa.qp = qpos;
    prep_kernel<<<dim3(1280, 1, 9), 256>>>(pa, Wt, Xh);

    // 2. QKV projections (word + entity in one launch) -> fp16 head layout
    GemmCfg cq = {};
    cq.bias0[0]=bq;  cq.bias0[1]=bk;  cq.bias0[2]=bv;
    cq.bias1[0]=beq; cq.bias1[1]=bek; cq.bias1[2]=bev;
    cq.o[0]=QH; cq.o[1]=KH; cq.o[2]=VH;
    cq.widx0 = 0; cq.widx1 = 3; cq.mode = 0; cq.ySplit = (NB*TW)/128;
    cq.Tseg0 = TW; cq.Tfull0 = TW; cq.toff0 = 0; cq.toffOut0 = 0;  cq.xb01_0 = 0;    cq.xb2_0 = 0;
    cq.Tseg1 = TE; cq.Tfull1 = TE; cq.toff1 = 0; cq.toffOut1 = TW; cq.xb01_1 = 4096; cq.xb2_1 = 4608;
    gemm_mma<<<dim3(8, (NB*TW + NB*TE)/128, 3), 256, SMEM_GEMM>>>(Xh, Wt, cq);

    // 3. attention (fp16) -> writes CTX fp16 directly into Xh rows [0, 4608)
    attn_tc<<<dim3(TT/128, NB*NHD), 256, ATTN_SMEM>>>(QH, KH, VH, mask, Xh);

    // 4. output projections (word + entity) + residual -> unified Y
    GemmCfg co = {};
    co.bias0[0]=bo; co.bias1[0]=beo;
    co.o[0]=Y;
    co.res0 = word; co.res1 = ent;
    co.widx0 = 6; co.widx1 = 7; co.mode = 1; co.ySplit = (NB*TW)/128;
    co.Tseg0 = TW; co.Tfull0 = TT; co.toff0 = 0;  co.xb01_0 = 0; co.xb2_0 = 0;
    co.Tseg1 = TE; co.Tfull1 = TT; co.toff1 = TW; co.xb01_1 = 0; co.xb2_1 = 0;
    co.outRowBase1 = NB*TW;
    gemm_mma<<<dim3(8, (NB*TW + NB*TE)/128, 1), 256, SMEM_GEMM>>>(Xh, Wt, co);

    // 5. layernorm (word + ent) -> d_out
    ln_kernel<<<NB*TW + NB*TE, 256>>>(Y, lng, lnb, elng, elnb, out);
}

// round 8
// speedup vs baseline: 10.9673x; 1.0639x over previous
#include <cuda_runtime.h>
#include <cuda_bf16.h>
#include <cuda_fp16.h>
#include <stdint.h>
#include <math.h>

#define NB  4
#define TW  1024
#define TE  128
#define TT  1152
#define HD  1024
#define NHD 16
#define DHD 64

// ---------------- scratch ----------------
__device__ float g_Y  [(NB*TW + NB*TE)*HD];   // unified pre-LN temp
__device__ __half g_QH[NB*NHD*TT*DHD];        // fp16 head-layout Q (pre-scaled 0.125*log2e)
__device__ __half g_KH[NB*NHD*TT*DHD];
__device__ __half g_VH[NB*NHD*TT*DHD];
__device__ __half g_Xh[5120*1024];
__device__ __half g_Wt[8*1024*1024];

// ---------------- helpers ----------------
__device__ __forceinline__ uint32_t smem_u32(const void* p){
    uint32_t a;
    asm("{ .reg .u64 t; cvta.to.shared.u64 t, %1; cvt.u32.u64 %0, t; }" : "=r"(a) : "l"(p));
    return a;
}
__device__ __forceinline__ uint32_t pkh(float a, float b){
    __half2 h = __floats2half2_rn(a, b);
    return *reinterpret_cast<uint32_t*>(&h);
}
__device__ __forceinline__ uint32_t ex2h2(uint32_t x){
    uint32_t r; asm("ex2.approx.f16x2 %0, %1;" : "=r"(r) : "r"(x)); return r;
}
__device__ __forceinline__ uint32_t hadd2u(uint32_t a, uint32_t b){
    uint32_t r; asm("add.f16x2 %0, %1, %2;" : "=r"(r) : "r"(a), "r"(b)); return r;
}
__device__ __forceinline__ float h2sumf(uint32_t h){
    __half2 v = *reinterpret_cast<__half2*>(&h);
    float2 f = __half22float2(v);
    return f.x + f.y;
}

#define CPA16(dst, src) asm volatile("cp.async.cg.shared.global [%0], [%1], 16;" :: "r"(dst), "l"(src))
#define CPA_COMMIT()    asm volatile("cp.async.commit_group;" ::: "memory")
template<int N> __device__ __forceinline__ void cpa_wait(){
    asm volatile("cp.async.wait_group %0;" :: "n"(N) : "memory");
}

__device__ __forceinline__ void ldsm4(uint32_t* r, uint32_t addr){
    asm volatile("ldmatrix.sync.aligned.m8n8.x4.shared.b16 {%0,%1,%2,%3}, [%4];"
        : "=r"(r[0]), "=r"(r[1]), "=r"(r[2]), "=r"(r[3]) : "r"(addr));
}
__device__ __forceinline__ void ldsm4t(uint32_t* r, uint32_t addr){
    asm volatile("ldmatrix.sync.aligned.m8n8.x4.trans.shared.b16 {%0,%1,%2,%3}, [%4];"
        : "=r"(r[0]), "=r"(r[1]), "=r"(r[2]), "=r"(r[3]) : "r"(addr));
}
__device__ __forceinline__ void mma16816h(float* d, const uint32_t* a, const uint32_t* b){
    asm volatile("mma.sync.aligned.m16n8k16.row.col.f32.f16.f16.f32 "
        "{%0,%1,%2,%3}, {%4,%5,%6,%7}, {%8,%9}, {%0,%1,%2,%3};"
        : "+f"(d[0]), "+f"(d[1]), "+f"(d[2]), "+f"(d[3])
        : "r"(a[0]), "r"(a[1]), "r"(a[2]), "r"(a[3]), "r"(b[0]), "r"(b[1]));
}

// ---------------- unified prep: weights (z<8) + activations (z==8) ----------------
struct PrepArgs {
    const float* w[8];
    const float* word; const float* ent; const float* qp;
};

__global__ __launch_bounds__(256) void prep_kernel(PrepArgs pa, __half* Wt, __half* Xh){
    __shared__ float tile[32][33];
    const int z = blockIdx.z;
    if (z < 8) {
        if (blockIdx.x >= 1024) return;
        const float* W = pa.w[z];
        int n0 = (blockIdx.x & 31) * 32, k0 = (blockIdx.x >> 5) * 32;
        int tx = threadIdx.x & 31, ty = threadIdx.x >> 5;
        #pragma unroll
        for (int i = 0; i < 32; i += 8)
            tile[ty + i][tx] = W[(size_t)(k0 + ty + i) * 1024 + n0 + tx];
        __syncthreads();
        #pragma unroll
        for (int i = 0; i < 32; i += 8) {
            float f = tile[tx][ty + i];
            size_t o = ((size_t)z << 20) + ((size_t)(n0 + ty + i) << 10) + k0 + tx;
            Wt[o] = __float2half_rn(f);
        }
    } else {
        size_t base4 = (size_t)blockIdx.x * 1024;
        #pragma unroll
        for (int i = 0; i < 4; i++) {
            size_t idx4 = base4 + threadIdx.x + i * 256;
            size_t row = idx4 >> 8;
            float4 v;
            if (row < 4096) {
                v = ((const float4*)pa.word)[idx4];
            } else if (row < 4608) {
                size_t off = idx4 - (size_t)4096 * 256;
                float4 a = ((const float4*)pa.ent)[off];
                float4 b = ((const float4*)pa.qp)[off];
                v = make_float4((a.x+b.x)*0.5f,(a.y+b.y)*0.5f,(a.z+b.z)*0.5f,(a.w+b.w)*0.5f);
            } else {
                size_t off = idx4 - (size_t)4608 * 256;
                v = ((const float4*)pa.ent)[off];
            }
            ((uint2*)Xh)[idx4] = make_uint2(pkh(v.x, v.y), pkh(v.z, v.w));
        }
    }
}

// ---------------- fp16 HMMA GEMM (two segments per launch) ----------------
#define STRB  144
#define OFF_B 18432
#define BUFSZ 36864
#define SMEM_GEMM (2*BUFSZ)

struct GemmCfg {
    const float* bias0[3]; const float* bias1[3];
    void* o[3];
    const float* res0; const float* res1;
    int widx0, widx1;
    int mode;
    int ySplit;
    int Tseg0, Tfull0, toff0, toffOut0, xb01_0, xb2_0;
    int Tseg1, Tfull1, toff1, toffOut1, xb01_1, xb2_1;
    int outRowBase1;
};

__global__ __launch_bounds__(256, 2) void gemm_mma(
    const __half* __restrict__ Xh, const __half* __restrict__ WtAll, GemmCfg cfg)
{
    extern __shared__ char smc[];
    const uint32_t sb = smem_u32(smc);
    const int tid = threadIdx.x;
    const int wid = tid >> 5, lane = tid & 31;
    const int wm = wid >> 1, wn = wid & 1;
    const int z = blockIdx.z;

    const int seg = (blockIdx.y >= cfg.ySplit) ? 1 : 0;
    const int yy  = seg ? blockIdx.y - cfg.ySplit : blockIdx.y;

    const float* bias = (seg ? cfg.bias1 : cfg.bias0)[z];
    void* out = cfg.o[z];
    const int Tseg    = seg ? cfg.Tseg1    : cfg.Tseg0;
    const int Tfull   = seg ? cfg.Tfull1   : cfg.Tfull0;
    const int toff    = seg ? cfg.toff1    : cfg.toff0;
    const int toffOut = seg ? cfg.toffOut1 : cfg.toffOut0;
    const int xb      = (z == 2) ? (seg ? cfg.xb2_1 : cfg.xb2_0)
                                 : (seg ? cfg.xb01_1 : cfg.xb01_0);
    const float* res  = seg ? cfg.res1 : cfg.res0;
    const int widx    = (seg ? cfg.widx1 : cfg.widx0) + z;
    const int outBase = seg ? cfg.outRowBase1 : 0;

    const __half* Wt = WtAll + ((size_t)widx << 20);
    // Q pre-scale folds 1/sqrt(d) AND log2(e) for the base-2 softmax
    const float oscale = (cfg.mode == 0 && z == 0) ? 0.125f * 1.44269504f : 1.f;

    const int m0 = yy * 128;
    const int n0 = blockIdx.x * 128;
    const int b2 = m0 / Tseg;
    const int t0 = m0 - b2 * Tseg;
    const __half* Ah = Xh + ((size_t)xb + (size_t)b2 * Tfull + toff + t0) * HD;

    float acc[2][8][4];
    #pragma unroll
    for (int mt = 0; mt < 2; mt++)
        #pragma unroll
        for (int nt = 0; nt < 8; nt++)
            #pragma unroll
            for (int j = 0; j < 4; j++) acc[mt][nt][j] = 0.f;

    auto issue_chunk = [&](int ch, int buf){
        const int k0 = ch * 64;
        const uint32_t base = sb + buf * BUFSZ;
        #pragma unroll
        for (int i = 0; i < 4; i++) {
            int q = tid + i * 256;
            int r = q >> 3, s8 = q & 7;
            CPA16(base + r * STRB + s8 * 16,         Ah + (size_t)r * HD + k0 + s8 * 8);
            CPA16(base + OFF_B + r * STRB + s8 * 16, Wt + (size_t)(n0 + r) * HD + k0 + s8 * 8);
        }
    };

    issue_chunk(0, 0);
    CPA_COMMIT();

    const int arow = (lane & 7) + ((lane >> 3) & 1) * 8;
    const int acol8 = (lane >> 4) * 8;
    const int bnof = (lane & 7) + ((lane >> 4) << 3);
    const int bk8  = ((lane >> 3) & 1) * 8;

    int buf = 0;
    for (int ch = 0; ch < 16; ch++) {
        if (ch < 15) { issue_chunk(ch + 1, buf ^ 1); CPA_COMMIT(); cpa_wait<1>(); }
        else         { cpa_wait<0>(); }
        __syncthreads();

        const uint32_t base = sb + buf * BUFSZ;
        #pragma unroll
        for (int ks = 0; ks < 4; ks++) {
            uint32_t aF[2][4];
            #pragma unroll
            for (int mt = 0; mt < 2; mt++)
                ldsm4(aF[mt], base + (wm*32 + mt*16 + arow) * STRB + (ks*16 + acol8) * 2);
            uint32_t bF[4][4];
            #pragma unroll
            for (int np = 0; np < 4; np++)
                ldsm4(bF[np], base + OFF_B + (wn*64 + np*16 + bnof) * STRB + (ks*16 + bk8) * 2);
            #pragma unroll
            for (int mt = 0; mt < 2; mt++)
                #pragma unroll
                for (int nt = 0; nt < 8; nt++)
                    mma16816h(acc[mt][nt], aF[mt], &bF[nt >> 1][(nt & 1) * 2]);
        }
        __syncthreads();
        buf ^= 1;
    }

    #pragma unroll
    for (int mt = 0; mt < 2; mt++) {
        #pragma unroll
        for (int hf = 0; hf < 2; hf++) {
            int lr = wm*32 + mt*16 + (lane >> 2) + hf*8;
            int t2 = t0 + lr;
            #pragma unroll
            for (int nt = 0; nt < 8; nt++) {
                int c = n0 + wn*64 + nt*8 + (lane & 3)*2;
                float v0 = acc[mt][nt][hf*2+0] + __ldg(bias + c);
                float v1 = acc[mt][nt][hf*2+1] + __ldg(bias + c + 1);
                if (cfg.mode == 0) {
                    int h = c >> 6, d = c & 63;
                    size_t o = (((size_t)(b2*NHD + h) * TT + toffOut + t2) << 6) + d;
                    *(uint32_t*)((__half*)out + o) = pkh(v0 * oscale, v1 * oscale);
                } else {
                    size_t ro = (size_t)(m0 + lr) * HD + c;
                    float2 rr = *(const float2*)(res + ro);
                    size_t oo = (size_t)(outBase + m0 + lr) * HD + c;
                    *(float2*)((float*)out + oo) = make_float2(v0 + rr.x, v1 + rr.y);
                }
            }
        }
    }
}

// ---------------- fp16 flash attention (FA2 register path, base-2 softmax) ----------------
#define AO_KF 18432
#define AO_VF 55296
#define ATTN_SMEM 92160
#define L2E 1.44269504f

__global__ __launch_bounds__(256, 2) void attn_tc(
    const __half* __restrict__ Q, const __half* __restrict__ K,
    const __half* __restrict__ V, const float* __restrict__ mask,
    __half* __restrict__ OutH)
{
    extern __shared__ char smc[];
    const uint32_t sbase = smem_u32(smc);

    const int tid = threadIdx.x, wid = tid >> 5, lane = tid & 31;
    const int bh = blockIdx.y, b = bh >> 4, h = bh & 15;
    const int q0 = blockIdx.x * 128;
    const __half* Qg = Q + ((size_t)bh * TT + q0) * DHD;
    const __half* Kg = K + (size_t)bh * TT * DHD;
    const __half* Vg = V + (size_t)bh * TT * DHD;
    const float* mb = mask + (size_t)b * TT;

    auto loadQ = [&](){
        #pragma unroll
        for (int i = 0; i < 4; i++) {
            int q = tid + i * 256;
            int r = q >> 3, s = q & 7;
            CPA16(sbase + r * STRB + s * 16, Qg + (size_t)r * DHD + s * 8);
        }
    };
    auto issueKV = [&](int ch, int buf){
        const __half* ks = Kg + (size_t)ch * 128 * DHD;
        const __half* vs = Vg + (size_t)ch * 128 * DHD;
        uint32_t kd = sbase + AO_KF + buf * 18432;
        uint32_t vd = sbase + AO_VF + buf * 18432;
        #pragma unroll
        for (int i = 0; i < 4; i++) {
            int q = tid + i * 256;
            int r = q >> 3, s = q & 7;
            CPA16(kd + r * STRB + s * 16, ks + (size_t)r * DHD + s * 8);
            CPA16(vd + r * STRB + s * 16, vs + (size_t)r * DHD + s * 8);
        }
        CPA_COMMIT();
    };

    loadQ();
    issueKV(0, 0);

    const int r4 = lane >> 2, c4 = lane & 3;
    const int row0 = wid * 16 + r4;
    const int arow16 = lane & 15, acol8 = (lane >> 4) * 8;
    const int bnof = (lane & 7) + ((lane >> 4) << 3);
    const int bk8  = ((lane >> 3) & 1) * 8;
    const int vgrp = lane >> 3, vwi = lane & 7;

    float O[8][4];
    #pragma unroll
    for (int nt = 0; nt < 8; nt++)
        #pragma unroll
        for (int j = 0; j < 4; j++) O[nt][j] = 0.f;
    float m0 = -1e30f, m1 = -1e30f, l0 = 0.f, l1 = 0.f;

    int buf = 0;
    for (int ch = 0; ch < 9; ch++) {
        if (ch > 0) __syncthreads();
        if (ch < 8) { issueKV(ch + 1, buf ^ 1); cpa_wait<1>(); }
        else        { cpa_wait<0>(); }
        __syncthreads();

        const uint32_t kb = sbase + AO_KF + buf * 18432;
        const uint32_t vb = sbase + AO_VF + buf * 18432;

        // ---- S = Qs @ K^T (Q pre-scaled by 0.125*log2e -> S in base-2) ----
        float S[16][4];
        #pragma unroll
        for (int nt = 0; nt < 16; nt++)
            #pragma unroll
            for (int j = 0; j < 4; j++) S[nt][j] = 0.f;

        {
            uint32_t aQ[4][4];
            #pragma unroll
            for (int ks = 0; ks < 4; ks++)
                ldsm4(aQ[ks], sbase + (wid*16 + arow16) * STRB + (ks*16 + acol8) * 2);
            #pragma unroll
            for (int ntp = 0; ntp < 8; ntp++) {
                #pragma unroll
                for (int ks = 0; ks < 4; ks++) {
                    uint32_t bF[4];
                    ldsm4(bF, kb + (ntp*16 + bnof) * STRB + (ks*16 + bk8) * 2);
                    mma16816h(S[2*ntp],     aQ[ks], &bF[0]);
                    mma16816h(S[2*ntp + 1], aQ[ks], &bF[2]);
                }
            }
        }

        // ---- mask (x log2e) + running max ----
        const int kgl = ch * 128;
        float mt0 = -1e30f, mt1 = -1e30f;
        #pragma unroll
        for (int nt = 0; nt < 16; nt++) {
            float2 mk = __ldg((const float2*)(mb + kgl + nt*8 + 2*c4));
            S[nt][0] = fmaf(mk.x, L2E, S[nt][0]);
            S[nt][1] = fmaf(mk.y, L2E, S[nt][1]);
            S[nt][2] = fmaf(mk.x, L2E, S[nt][2]);
            S[nt][3] = fmaf(mk.y, L2E, S[nt][3]);
            mt0 = fmaxf(mt0, fmaxf(S[nt][0], S[nt][1]));
            mt1 = fmaxf(mt1, fmaxf(S[nt][2], S[nt][3]));
        }
        mt0 = fmaxf(mt0, __shfl_xor_sync(0xffffffffu, mt0, 1));
        mt0 = fmaxf(mt0, __shfl_xor_sync(0xffffffffu, mt0, 2));
        mt1 = fmaxf(mt1, __shfl_xor_sync(0xffffffffu, mt1, 1));
        mt1 = fmaxf(mt1, __shfl_xor_sync(0xffffffffu, mt1, 2));

        float mn0 = fmaxf(m0, mt0), mn1 = fmaxf(m1, mt1);
        float al0 = exp2f(m0 - mn0), al1 = exp2f(m1 - mn1);
        #pragma unroll
        for (int nt = 0; nt < 8; nt++) {
            O[nt][0] *= al0; O[nt][1] *= al0;
            O[nt][2] *= al1; O[nt][3] *= al1;
        }

        // ---- P = exp2(S - mn) packed fp16 pairs (ex2.approx.f16x2) ----
        uint32_t P16[8][4];
        #pragma unroll
        for (int t = 0; t < 8; t++) {
            P16[t][0] = ex2h2(pkh(S[2*t][0]   - mn0, S[2*t][1]   - mn0));
            P16[t][1] = ex2h2(pkh(S[2*t][2]   - mn1, S[2*t][3]   - mn1));
            P16[t][2] = ex2h2(pkh(S[2*t+1][0] - mn0, S[2*t+1][1] - mn0));
            P16[t][3] = ex2h2(pkh(S[2*t+1][2] - mn1, S[2*t+1][3] - mn1));
        }

        // ---- l via HADD2 tree ----
        {
            uint32_t q0a[8], q1a[8];
            #pragma unroll
            for (int t = 0; t < 8; t++) {
                q0a[t] = hadd2u(P16[t][0], P16[t][2]);
                q1a[t] = hadd2u(P16[t][1], P16[t][3]);
            }
            uint32_t s0 = hadd2u(hadd2u(hadd2u(q0a[0], q0a[1]), hadd2u(q0a[2], q0a[3])),
                                 hadd2u(hadd2u(q0a[4], q0a[5]), hadd2u(q0a[6], q0a[7])));
            uint32_t s1 = hadd2u(hadd2u(hadd2u(q1a[0], q1a[1]), hadd2u(q1a[2], q1a[3])),
                                 hadd2u(hadd2u(q1a[4], q1a[5]), hadd2u(q1a[6], q1a[7])));
            float ls0 = h2sumf(s0), ls1 = h2sumf(s1);
            ls0 += __shfl_xor_sync(0xffffffffu, ls0, 1);
            ls0 += __shfl_xor_sync(0xffffffffu, ls0, 2);
            ls1 += __shfl_xor_sync(0xffffffffu, ls1, 1);
            ls1 += __shfl_xor_sync(0xffffffffu, ls1, 2);
            l0 = l0 * al0 + ls0; m0 = mn0;
            l1 = l1 * al1 + ls1; m1 = mn1;
        }

        // ---- O += P @ V ----
        #pragma unroll
        for (int t = 0; t < 8; t++) {
            #pragma unroll
            for (int dp = 0; dp < 4; dp++) {
                uint32_t bF[4];
                ldsm4t(bF, vb + (t*16 + (vgrp & 1)*8 + vwi) * STRB + (dp*16 + (vgrp >> 1)*8) * 2);
                mma16816h(O[2*dp],     P16[t], &bF[0]);
                mma16816h(O[2*dp + 1], P16[t], &bF[2]);
            }
        }
        buf ^= 1;
    }

    float i0 = 1.f / l0, i1 = 1.f / l1;
    #pragma unroll
    for (int nt = 0; nt < 8; nt++) {
        int c = h * 64 + nt*8 + 2*c4;
        size_t o0 = (size_t)(b * TT + q0 + row0) * HD + c;
        size_t o1 = (size_t)(b * TT + q0 + row0 + 8) * HD + c;
        *(uint32_t*)(OutH + o0) = pkh(O[nt][0] * i0, O[nt][1] * i0);
        *(uint32_t*)(OutH + o1) = pkh(O[nt][2] * i1, O[nt][3] * i1);
    }
}

// ---------------- layernorm (unified word+ent) ----------------
__device__ __forceinline__ float block_sum(float v, float* sh) {
    #pragma unroll
    for (int o = 16; o; o >>= 1) v += __shfl_xor_sync(0xffffffffu, v, o);
    int tid = threadIdx.x;
    if ((tid & 31) == 0) sh[tid >> 5] = v;
    __syncthreads();
    if (tid < 32) {
        float t = (tid < 8) ? sh[tid] : 0.f;
        #pragma unroll
        for (int o = 4; o; o >>= 1) t += __shfl_xor_sync(0xffffffffu, t, o);
        if (tid == 0) sh[0] = t;
    }
    __syncthreads();
    float r = sh[0];
    __syncthreads();
    return r;
}

__global__ __launch_bounds__(256) void ln_kernel(
    const float* __restrict__ Y,
    const float* __restrict__ g0, const float* __restrict__ b0,
    const float* __restrict__ g1, const float* __restrict__ b1,
    float* __restrict__ out)
{
    __shared__ float sh[8];
    int row = blockIdx.x, tid = threadIdx.x;
    const float* g  = (row < NB*TW) ? g0 : g1;
    const float* bt = (row < NB*TW) ? b0 : b1;
    float4 v = ((const float4*)(Y + (size_t)row * HD))[tid];
    float mu = block_sum(v.x + v.y + v.z + v.w, sh) * (1.f / HD);
    float4 d = make_float4(v.x - mu, v.y - mu, v.z - mu, v.w - mu);
    float var = block_sum(d.x*d.x + d.y*d.y + d.z*d.z + d.w*d.w, sh) * (1.f / HD);
    float rs = rsqrtf(var + 1e-12f);
    float4 gg = ((const float4*)g)[tid];
    float4 bb = ((const float4*)bt)[tid];
    ((float4*)(out + (size_t)row * HD))[tid] =
        make_float4(d.x*rs*gg.x + bb.x, d.y*rs*gg.y + bb.y, d.z*rs*gg.z + bb.z, d.w*rs*gg.w + bb.w);
}

// ---------------- launch ----------------
extern "C" void kernel_launch(void* const* d_in, const int* in_sizes, int n_in,
                              void* d_out, int out_size)
{
    (void)in_sizes; (void)n_in; (void)out_size;
    const float* word = (const float*)d_in[0];
    const float* ent  = (const float*)d_in[1];
    const float* mask = (const float*)d_in[2];
    const float* qpos = (const float*)d_in[3];
    const float* Wq  = (const float*)d_in[4];   const float* bq  = (const float*)d_in[5];
    const float* Wk  = (const float*)d_in[6];   const float* bk  = (const float*)d_in[7];
    const float* Wv  = (const float*)d_in[8];   const float* bv  = (const float*)d_in[9];
    const float* Weq = (const float*)d_in[10];  const float* beq = (const float*)d_in[11];
    const float* Wek = (const float*)d_in[12];  const float* bek = (const float*)d_in[13];
    const float* Wev = (const float*)d_in[14];  const float* bev = (const float*)d_in[15];
    const float* Wo  = (const float*)d_in[16];  const float* bo  = (const float*)d_in[17];
    const float* Weo = (const float*)d_in[18];  const float* beo = (const float*)d_in[19];
    const float* lng  = (const float*)d_in[20]; const float* lnb  = (const float*)d_in[21];
    const float* elng = (const float*)d_in[22]; const float* elnb = (const float*)d_in[23];
    float* out = (float*)d_out;

    float *Y;
    __half *QH, *KH, *VH, *Xh, *Wt;
    cudaGetSymbolAddress((void**)&Y,  g_Y);
    cudaGetSymbolAddress((void**)&QH, g_QH);
    cudaGetSymbolAddress((void**)&KH, g_KH);
    cudaGetSymbolAddress((void**)&VH, g_VH);
    cudaGetSymbolAddress((void**)&Xh, g_Xh);
    cudaGetSymbolAddress((void**)&Wt, g_Wt);

    cudaFuncSetAttribute(gemm_mma, cudaFuncAttributeMaxDynamicSharedMemorySize, SMEM_GEMM);
    cudaFuncSetAttribute(attn_tc, cudaFuncAttributeMaxDynamicSharedMemorySize, ATTN_SMEM);

    // 1. unified prep
    PrepArgs pa;
    pa.w[0]=Wq; pa.w[1]=Wk; pa.w[2]=Wv; pa.w[3]=Weq; pa.w[4]=Wek; pa.w[5]=Wev; pa.w[6]=Wo; pa.w[7]=Weo;
    pa.word = word; pa.ent = ent; pa.qp = qpos;
    prep_kernel<<<dim3(1280, 1, 9), 256>>>(pa, Wt, Xh);

    // 2. QKV projections (word + entity) -> fp16 head layout
    GemmCfg cq = {};
    cq.bias0[0]=bq;  cq.bias0[1]=bk;  cq.bias0[2]=bv;
    cq.bias1[0]=beq; cq.bias1[1]=bek; cq.bias1[2]=bev;
    cq.o[0]=QH; cq.o[1]=KH; cq.o[2]=VH;
    cq.widx0 = 0; cq.widx1 = 3; cq.mode = 0; cq.ySplit = (NB*TW)/128;
    cq.Tseg0 = TW; cq.Tfull0 = TW; cq.toff0 = 0; cq.toffOut0 = 0;  cq.xb01_0 = 0;    cq.xb2_0 = 0;
    cq.Tseg1 = TE; cq.Tfull1 = TE; cq.toff1 = 0; cq.toffOut1 = TW; cq.xb01_1 = 4096; cq.xb2_1 = 4608;
    gemm_mma<<<dim3(8, (NB*TW + NB*TE)/128, 3), 256, SMEM_GEMM>>>(Xh, Wt, cq);

    // 3. attention (fp16, base-2 softmax) -> CTX fp16 into Xh rows [0, 4608)
    attn_tc<<<dim3(TT/128, NB*NHD), 256, ATTN_SMEM>>>(QH, KH, VH, mask, Xh);

    // 4. output projections + residual -> unified Y
    GemmCfg co = {};
    co.bias0[0]=bo; co.bias1[0]=beo;
    co.o[0]=Y;
    co.res0 = word; co.res1 = ent;
    co.widx0 = 6; co.widx1 = 7; co.mode = 1; co.ySplit = (NB*TW)/128;
    co.Tseg0 = TW; co.Tfull0 = TT; co.toff0 = 0;  co.xb01_0 = 0; co.xb2_0 = 0;
    co.Tseg1 = TE; co.Tfull1 = TT; co.toff1 = TW; co.xb01_1 = 0; co.xb2_1 = 0;
    co.outRowBase1 = NB*TW;
    gemm_mma<<<dim3(8, (NB*TW + NB*TE)/128, 1), 256, SMEM_GEMM>>>(Xh, Wt, co);

    // 5. layernorm -> d_out
    ln_kernel<<<NB*TW + NB*TE, 256>>>(Y, lng, lnb, elng, elnb, out);
}